// round 3
// baseline (speedup 1.0000x reference)
#include <cuda_runtime.h>
#include <math.h>

#define N_RAYS 4096
#define N_SAMPLES 192
#define GRID_D 160
#define GRID_D2 (160*160)
#define GRID_D3 (160*160*160)
#define K0_DIM 12
#define WIDTH 128
#define DIM0 39
#define XYZ_MIN (-1.2f)
#define COORD_SCALE (159.0f / 2.4f)
#define ACT_SHIFT (-4.595119850134589f)
#define STEPDIST (2.8f / 192.0f)
#define NEARV 0.2f
#define FARV 3.0f

#define NPTS (N_RAYS * N_SAMPLES)

// scratch (no dynamic allocation allowed)
__device__ float g_alpha[NPTS];
__device__ float g_rgb0[NPTS];
__device__ float g_rgb1[NPTS];
__device__ float g_rgb2[NPTS];

// SMEM layout (floats):
// w1s[16384] w0s[4992] w2s[384] b0s[128] b1s[128] b2s[4] hbuf[128*129]
#define SM_W1 0
#define SM_W0 16384
#define SM_W2 (16384 + 4992)
#define SM_B0 (SM_W2 + 384)
#define SM_B1 (SM_B0 + 128)
#define SM_B2 (SM_B1 + 128)
#define SM_H  (SM_B2 + 4)
#define SM_FLOATS (SM_H + 128 * 129)
#define SMEM_BYTES (SM_FLOATS * 4)

__global__ void __launch_bounds__(128, 1)
point_kernel(const float* __restrict__ rays_o,
             const float* __restrict__ rays_d,
             const float* __restrict__ dgrid,
             const float* __restrict__ k0grid,
             const float* __restrict__ w0,
             const float* __restrict__ b0,
             const float* __restrict__ w1,
             const float* __restrict__ b1,
             const float* __restrict__ w2,
             const float* __restrict__ b2)
{
    extern __shared__ float sm[];
    const int tid = threadIdx.x;

    // ---- stage weights into SMEM (completion deferred: sync is just before
    // layer 0, so these long-scoreboard loads overlap the trilerp gathers) ----
    for (int i = tid; i < 16384; i += 128) sm[SM_W1 + i] = w1[i];
    for (int i = tid; i < 4992;  i += 128) sm[SM_W0 + i] = w0[i];
    for (int i = tid; i < 384;   i += 128) sm[SM_W2 + i] = w2[i];
    sm[SM_B0 + tid] = b0[tid];
    sm[SM_B1 + tid] = b1[tid];
    if (tid < 3) sm[SM_B2 + tid] = b2[tid];

    const int idx = blockIdx.x * 128 + tid;   // grid is exact: 6144*128 = NPTS
    const int r = idx / N_SAMPLES;
    const int s = idx - r * N_SAMPLES;

    // ---- ray point ----
    float dx = rays_d[r * 3 + 0], dy = rays_d[r * 3 + 1], dz = rays_d[r * 3 + 2];
    const float inv = rsqrtf(dx * dx + dy * dy + dz * dz);
    const float vx = dx * inv, vy = dy * inv, vz = dz * inv;
    const float tval = NEARV + (FARV - NEARV) * ((float)s + 0.5f) / (float)N_SAMPLES;
    float px = rays_o[r * 3 + 0] + vx * tval;
    float py = rays_o[r * 3 + 1] + vy * tval;
    float pz = rays_o[r * 3 + 2] + vz * tval;
    const float nrm = fmaxf(fabsf(px), fmaxf(fabsf(py), fabsf(pz)));
    if (nrm > 1.0f) {
        const float invn = 1.0f / nrm;
        const float sc = (1.2f - 0.2f * invn) * invn;
        px *= sc; py *= sc; pz *= sc;
    }

    // ---- trilerp setup ----
    float gx = (px - XYZ_MIN) * COORD_SCALE;
    float gy = (py - XYZ_MIN) * COORD_SCALE;
    float gz = (pz - XYZ_MIN) * COORD_SCALE;
    gx = fminf(fmaxf(gx, 0.0f), 159.0f);
    gy = fminf(fmaxf(gy, 0.0f), 159.0f);
    gz = fminf(fmaxf(gz, 0.0f), 159.0f);
    const int ix = min((int)floorf(gx), 158);
    const int iy = min((int)floorf(gy), 158);
    const int iz = min((int)floorf(gz), 158);
    const float fx = gx - (float)ix, fy = gy - (float)iy, fz = gz - (float)iz;
    const float ex = 1.0f - fx, ey = 1.0f - fy, ez = 1.0f - fz;
    const int base = ix * GRID_D2 + iy * GRID_D + iz;
    const float w000 = ex * ey * ez, w100 = fx * ey * ez;
    const float w010 = ex * fy * ez, w001 = ex * ey * fz;
    const float w110 = fx * fy * ez, w101 = fx * ey * fz;
    const float w011 = ex * fy * fz, w111 = fx * fy * fz;

    // ---- density -> alpha ----
    {
        const float* g = dgrid + base;
        const float dv = g[0] * w000 + g[GRID_D2] * w100 + g[GRID_D] * w010 + g[1] * w001
                       + g[GRID_D2 + GRID_D] * w110 + g[GRID_D2 + 1] * w101
                       + g[GRID_D + 1] * w011 + g[GRID_D2 + GRID_D + 1] * w111;
        const float x = dv + ACT_SHIFT;
        const float sigma = fmaxf(x, 0.0f) + log1pf(__expf(-fabsf(x)));
        const float alpha = 1.0f - __expf(-sigma * STEPDIST);
        g_alpha[idx] = alpha;
    }

    // ---- features ----
    float feat[DIM0];
#pragma unroll
    for (int c = 0; c < K0_DIM; c++) {
        const float* g = k0grid + c * GRID_D3 + base;
        feat[c] = g[0] * w000 + g[GRID_D2] * w100 + g[GRID_D] * w010 + g[1] * w001
                + g[GRID_D2 + GRID_D] * w110 + g[GRID_D2 + 1] * w101
                + g[GRID_D + 1] * w011 + g[GRID_D2 + GRID_D + 1] * w111;
    }
    feat[12] = vx; feat[13] = vy; feat[14] = vz;
    {
        const float v3[3] = {vx, vy, vz};
#pragma unroll
        for (int i = 0; i < 3; i++) {
#pragma unroll
            for (int p = 0; p < 4; p++) {
                const float ang = v3[i] * (float)(1 << p);
                float sv, cv;
                __sincosf(ang, &sv, &cv);
                feat[15 + i * 4 + p] = sv;
                feat[27 + i * 4 + p] = cv;
            }
        }
    }

    __syncthreads();   // weights staged + hbuf region safe to write

    // ---- layer 0: 39 -> 128 (into SMEM h-buffer, stride 129) ----
    float* hrow = &sm[SM_H + tid * 129];
    for (int cb = 0; cb < 16; cb++) {
        const int col = cb * 8;
        float acc[8];
#pragma unroll
        for (int j = 0; j < 8; j++) acc[j] = sm[SM_B0 + col + j];
#pragma unroll
        for (int k = 0; k < DIM0; k++) {
            const float4 wa = *(const float4*)&sm[SM_W0 + k * 128 + col];
            const float4 wb = *(const float4*)&sm[SM_W0 + k * 128 + col + 4];
            const float fk = feat[k];
            acc[0] += fk * wa.x; acc[1] += fk * wa.y;
            acc[2] += fk * wa.z; acc[3] += fk * wa.w;
            acc[4] += fk * wb.x; acc[5] += fk * wb.y;
            acc[6] += fk * wb.z; acc[7] += fk * wb.w;
        }
#pragma unroll
        for (int j = 0; j < 8; j++) hrow[col + j] = fmaxf(acc[j], 0.0f);
    }

    // ---- layer 1 (128->128) fused with layer 2 (128->3) ----
    // hrow is private to this thread: no barrier needed between layer0 and layer1.
    float r0 = sm[SM_B2 + 0], r1 = sm[SM_B2 + 1], r2 = sm[SM_B2 + 2];
    for (int cb = 0; cb < 8; cb++) {
        const int col = cb * 16;
        float acc[16];
#pragma unroll
        for (int j = 0; j < 16; j++) acc[j] = sm[SM_B1 + col + j];
#pragma unroll 4
        for (int k = 0; k < WIDTH; k++) {
            const float hk = hrow[k];
            const float4 wa = *(const float4*)&sm[SM_W1 + k * 128 + col];
            const float4 wb = *(const float4*)&sm[SM_W1 + k * 128 + col + 4];
            const float4 wc = *(const float4*)&sm[SM_W1 + k * 128 + col + 8];
            const float4 wd = *(const float4*)&sm[SM_W1 + k * 128 + col + 12];
            acc[0]  += hk * wa.x; acc[1]  += hk * wa.y; acc[2]  += hk * wa.z; acc[3]  += hk * wa.w;
            acc[4]  += hk * wb.x; acc[5]  += hk * wb.y; acc[6]  += hk * wb.z; acc[7]  += hk * wb.w;
            acc[8]  += hk * wc.x; acc[9]  += hk * wc.y; acc[10] += hk * wc.z; acc[11] += hk * wc.w;
            acc[12] += hk * wd.x; acc[13] += hk * wd.y; acc[14] += hk * wd.z; acc[15] += hk * wd.w;
        }
#pragma unroll
        for (int j = 0; j < 16; j++) {
            const float h = fmaxf(acc[j], 0.0f);
            const int kk = col + j;
            r0 += h * sm[SM_W2 + kk * 3 + 0];
            r1 += h * sm[SM_W2 + kk * 3 + 1];
            r2 += h * sm[SM_W2 + kk * 3 + 2];
        }
    }

    g_rgb0[idx] = 1.0f / (1.0f + __expf(-r0));
    g_rgb1[idx] = 1.0f / (1.0f + __expf(-r1));
    g_rgb2[idx] = 1.0f / (1.0f + __expf(-r2));
}

// ---- compositing: one warp per ray ----
__global__ void __launch_bounds__(256)
composite_kernel(float* __restrict__ out)
{
    const int gwarp = (blockIdx.x * blockDim.x + threadIdx.x) >> 5;
    const int lane = threadIdx.x & 31;
    if (gwarp >= N_RAYS) return;
    const int r = gwarp;

    float T = 1.0f, wsum = 0.0f, a0 = 0.0f, a1 = 0.0f, a2 = 0.0f;
#pragma unroll
    for (int chunk = 0; chunk < N_SAMPLES / 32; chunk++) {
        const int off = r * N_SAMPLES + chunk * 32 + lane;
        const float alpha = g_alpha[off];
        const float c0 = g_rgb0[off];
        const float c1 = g_rgb1[off];
        const float c2 = g_rgb2[off];
        float p = 1.0f - alpha + 1e-10f;
        // inclusive prefix product across the warp
#pragma unroll
        for (int d = 1; d < 32; d <<= 1) {
            const float up = __shfl_up_sync(0xFFFFFFFFu, p, d);
            if (lane >= d) p *= up;
        }
        float excl = __shfl_up_sync(0xFFFFFFFFu, p, 1);
        if (lane == 0) excl = 1.0f;
        const float Tl = T * excl;
        const float w = alpha * Tl;
        wsum += w;
        a0 += w * c0; a1 += w * c1; a2 += w * c2;
        T *= __shfl_sync(0xFFFFFFFFu, p, 31);
    }
    // warp reduce
#pragma unroll
    for (int d = 16; d > 0; d >>= 1) {
        wsum += __shfl_down_sync(0xFFFFFFFFu, wsum, d);
        a0 += __shfl_down_sync(0xFFFFFFFFu, a0, d);
        a1 += __shfl_down_sync(0xFFFFFFFFu, a1, d);
        a2 += __shfl_down_sync(0xFFFFFFFFu, a2, d);
    }
    if (lane == 0) {
        const float bg = 1.0f - wsum;
        out[r * 3 + 0] = a0 + bg;
        out[r * 3 + 1] = a1 + bg;
        out[r * 3 + 2] = a2 + bg;
    }
}

extern "C" void kernel_launch(void* const* d_in, const int* in_sizes, int n_in,
                              void* d_out, int out_size)
{
    const float* rays_o = (const float*)d_in[0];
    const float* rays_d = (const float*)d_in[1];
    const float* dgrid  = (const float*)d_in[2];
    const float* k0grid = (const float*)d_in[3];
    const float* w0 = (const float*)d_in[4];
    const float* b0 = (const float*)d_in[5];
    const float* w1 = (const float*)d_in[6];
    const float* b1 = (const float*)d_in[7];
    const float* w2 = (const float*)d_in[8];
    const float* b2 = (const float*)d_in[9];
    float* out = (float*)d_out;

    cudaFuncSetAttribute(point_kernel,
                         cudaFuncAttributeMaxDynamicSharedMemorySize, SMEM_BYTES);

    point_kernel<<<NPTS / 128, 128, SMEM_BYTES>>>(rays_o, rays_d, dgrid, k0grid,
                                                  w0, b0, w1, b1, w2, b2);
    composite_kernel<<<(N_RAYS * 32 + 255) / 256, 256>>>(out);
}

// round 6
// speedup vs baseline: 2.6909x; 2.6909x over previous
#include <cuda_runtime.h>
#include <cstdint>
#include <math.h>

#define N_RAYS 4096
#define N_SAMPLES 192
#define GRID_D 160
#define GRID_D2 (160*160)
#define GRID_D3 (160*160*160)
#define K0_DIM 12
#define XYZ_MIN (-1.2f)
#define COORD_SCALE (159.0f / 2.4f)
#define ACT_SHIFT (-4.595119850134589f)
#define STEPDIST (2.8f / 192.0f)
#define NEARV 0.2f
#define FARV 3.0f

#define NPTS (N_RAYS * N_SAMPLES)

// ---------------- scratch ----------------
__device__ float g_alpha[NPTS];
__device__ float g_rgb0[NPTS];
__device__ float g_rgb1[NPTS];
__device__ float g_rgb2[NPTS];
// prepacked transposed tf32 weights, padded strides for conflict-free LDS
__device__ uint32_t PW0T[128 * 44];    // [n][k], k<39 real
__device__ uint32_t PW1T[128 * 132];   // [n][k], k<128 real

// ---------------- smem layout (float units) ----------------
#define SM_W0T 0
#define SM_W1T 5632
#define SM_W2  22528
#define SM_B0  22912
#define SM_B1  23040
#define SM_B2  23168
#define SM_F   23172
#define SM_H   28804
#define SM_FLOATS 45700
#define SMEM_BYTES (SM_FLOATS * 4)

__device__ __forceinline__ uint32_t cvt_tf32(float x) {
    uint32_t u;
    asm("cvt.rna.tf32.f32 %0, %1;" : "=r"(u) : "f"(x));
    return u;
}

__device__ __forceinline__ void mma_tf32(float c[4],
                                         uint32_t a0, uint32_t a1, uint32_t a2, uint32_t a3,
                                         uint32_t b0, uint32_t b1) {
    asm volatile("mma.sync.aligned.m16n8k8.row.col.f32.tf32.tf32.f32 "
                 "{%0,%1,%2,%3}, {%4,%5,%6,%7}, {%8,%9}, {%0,%1,%2,%3};"
                 : "+f"(c[0]), "+f"(c[1]), "+f"(c[2]), "+f"(c[3])
                 : "r"(a0), "r"(a1), "r"(a2), "r"(a3), "r"(b0), "r"(b1));
}

// ---------------- prep: pack W0^T / W1^T tf32, padded ----------------
__global__ void prep_kernel(const float* __restrict__ w0, const float* __restrict__ w1)
{
    const int t = blockIdx.x * blockDim.x + threadIdx.x;
    const int stride = gridDim.x * blockDim.x;
    for (int i = t; i < 128 * 44; i += stride) {
        const int n = i / 44, k = i - n * 44;
        PW0T[i] = (k < 39) ? cvt_tf32(w0[k * 128 + n]) : 0u;
    }
    for (int i = t; i < 128 * 132; i += stride) {
        const int n = i / 132, k = i - n * 132;
        PW1T[i] = (k < 128) ? cvt_tf32(w1[k * 128 + n]) : 0u;
    }
}

// ---------------- point kernel: 128 samples / block ----------------
__global__ void __launch_bounds__(128, 1)
point_kernel(const float* __restrict__ rays_o,
             const float* __restrict__ rays_d,
             const float* __restrict__ dgrid,
             const float* __restrict__ k0grid,
             const float* __restrict__ w2,
             const float* __restrict__ b0,
             const float* __restrict__ b1,
             const float* __restrict__ b2)
{
    extern __shared__ float sm[];
    const int tid = threadIdx.x;

    // ---- stage prepacked weights (coalesced; completes at the syncthreads) ----
    {
        float4* d0 = (float4*)(sm + SM_W0T);
        const float4* s0 = (const float4*)PW0T;
        for (int i = tid; i < 1408; i += 128) d0[i] = s0[i];
        float4* d1 = (float4*)(sm + SM_W1T);
        const float4* s1 = (const float4*)PW1T;
        for (int i = tid; i < 4224; i += 128) d1[i] = s1[i];
    }
    for (int i = tid; i < 384; i += 128) sm[SM_W2 + i] = w2[i];
    sm[SM_B0 + tid] = b0[tid];
    sm[SM_B1 + tid] = b1[tid];
    if (tid < 3) sm[SM_B2 + tid] = b2[tid];

    // ---- per-sample point / trilerp / features ----
    const int idx = blockIdx.x * 128 + tid;
    const int r = idx / N_SAMPLES;
    const int s = idx - r * N_SAMPLES;

    float dx = rays_d[r * 3 + 0], dy = rays_d[r * 3 + 1], dz = rays_d[r * 3 + 2];
    const float inv = rsqrtf(dx * dx + dy * dy + dz * dz);
    const float vx = dx * inv, vy = dy * inv, vz = dz * inv;
    const float tval = NEARV + (FARV - NEARV) * ((float)s + 0.5f) / (float)N_SAMPLES;
    float px = rays_o[r * 3 + 0] + vx * tval;
    float py = rays_o[r * 3 + 1] + vy * tval;
    float pz = rays_o[r * 3 + 2] + vz * tval;
    const float nrm = fmaxf(fabsf(px), fmaxf(fabsf(py), fabsf(pz)));
    if (nrm > 1.0f) {
        const float invn = 1.0f / nrm;
        const float sc = (1.2f - 0.2f * invn) * invn;
        px *= sc; py *= sc; pz *= sc;
    }
    float gx = (px - XYZ_MIN) * COORD_SCALE;
    float gy = (py - XYZ_MIN) * COORD_SCALE;
    float gz = (pz - XYZ_MIN) * COORD_SCALE;
    gx = fminf(fmaxf(gx, 0.0f), 159.0f);
    gy = fminf(fmaxf(gy, 0.0f), 159.0f);
    gz = fminf(fmaxf(gz, 0.0f), 159.0f);
    const int ix = min((int)floorf(gx), 158);
    const int iy = min((int)floorf(gy), 158);
    const int iz = min((int)floorf(gz), 158);
    const float fx = gx - (float)ix, fy = gy - (float)iy, fz = gz - (float)iz;
    const float ex = 1.0f - fx, ey = 1.0f - fy, ez = 1.0f - fz;
    const int base = ix * GRID_D2 + iy * GRID_D + iz;
    const float w000 = ex * ey * ez, w100 = fx * ey * ez;
    const float w010 = ex * fy * ez, w001 = ex * ey * fz;
    const float w110 = fx * fy * ez, w101 = fx * ey * fz;
    const float w011 = ex * fy * fz, w111 = fx * fy * fz;

    {
        const float* g = dgrid + base;
        const float dv = g[0] * w000 + g[GRID_D2] * w100 + g[GRID_D] * w010 + g[1] * w001
                       + g[GRID_D2 + GRID_D] * w110 + g[GRID_D2 + 1] * w101
                       + g[GRID_D + 1] * w011 + g[GRID_D2 + GRID_D + 1] * w111;
        const float x = dv + ACT_SHIFT;
        const float sigma = fmaxf(x, 0.0f) + log1pf(__expf(-fabsf(x)));
        g_alpha[idx] = 1.0f - __expf(-sigma * STEPDIST);
    }

    float feat[40];
#pragma unroll
    for (int c = 0; c < K0_DIM; c++) {
        const float* g = k0grid + c * GRID_D3 + base;
        feat[c] = g[0] * w000 + g[GRID_D2] * w100 + g[GRID_D] * w010 + g[1] * w001
                + g[GRID_D2 + GRID_D] * w110 + g[GRID_D2 + 1] * w101
                + g[GRID_D + 1] * w011 + g[GRID_D2 + GRID_D + 1] * w111;
    }
    feat[12] = vx; feat[13] = vy; feat[14] = vz;
    {
        const float v3[3] = {vx, vy, vz};
#pragma unroll
        for (int i = 0; i < 3; i++) {
#pragma unroll
            for (int p = 0; p < 4; p++) {
                float sv, cv;
                __sincosf(v3[i] * (float)(1 << p), &sv, &cv);
                feat[15 + i * 4 + p] = sv;
                feat[27 + i * 4 + p] = cv;
            }
        }
    }
    feat[39] = 0.0f;

    // feature row -> smem (tf32), row = tid, stride 44
    {
        uint32_t* F = (uint32_t*)(sm + SM_F);
#pragma unroll
        for (int j = 0; j < 40; j++) F[tid * 44 + j] = cvt_tf32(feat[j]);
    }

    __syncthreads();

    const int lane = tid & 31;
    const int warp = tid >> 5;
    const int g8 = lane >> 2;      // groupID 0..7
    const int q = lane & 3;        // threadID_in_group
    const int m0 = warp * 32;

    const uint32_t* F   = (const uint32_t*)(sm + SM_F);
    const uint32_t* W0T = (const uint32_t*)(sm + SM_W0T);
    const uint32_t* W1T = (const uint32_t*)(sm + SM_W1T);
    uint32_t* H = (uint32_t*)(sm + SM_H);

    // ---- layer 0: [128x40] @ [40x128], mma.sync tf32 ----
    uint32_t af[2][5][4];
#pragma unroll
    for (int t = 0; t < 2; t++) {
        const int r0 = m0 + 16 * t;
#pragma unroll
        for (int kk = 0; kk < 5; kk++) {
            const int k = kk * 8 + q;
            af[t][kk][0] = F[(r0 + g8) * 44 + k];
            af[t][kk][1] = F[(r0 + 8 + g8) * 44 + k];
            af[t][kk][2] = F[(r0 + g8) * 44 + k + 4];
            af[t][kk][3] = F[(r0 + 8 + g8) * 44 + k + 4];
        }
    }
#pragma unroll
    for (int nt = 0; nt < 16; nt++) {
        const int n0 = nt * 8;
        const float cb0 = sm[SM_B0 + n0 + 2 * q];
        const float cb1 = sm[SM_B0 + n0 + 2 * q + 1];
        float C0[4] = {cb0, cb1, cb0, cb1};
        float C1[4] = {cb0, cb1, cb0, cb1};
#pragma unroll
        for (int kk = 0; kk < 5; kk++) {
            const int k = kk * 8 + q;
            const uint32_t bb0 = W0T[(n0 + g8) * 44 + k];
            const uint32_t bb1 = W0T[(n0 + g8) * 44 + k + 4];
            mma_tf32(C0, af[0][kk][0], af[0][kk][1], af[0][kk][2], af[0][kk][3], bb0, bb1);
            mma_tf32(C1, af[1][kk][0], af[1][kk][1], af[1][kk][2], af[1][kk][3], bb0, bb1);
        }
        // relu -> tf32 -> H (stride 132), rows are warp-private
        H[(m0 + g8) * 132 + n0 + 2 * q]          = cvt_tf32(fmaxf(C0[0], 0.0f));
        H[(m0 + g8) * 132 + n0 + 2 * q + 1]      = cvt_tf32(fmaxf(C0[1], 0.0f));
        H[(m0 + 8 + g8) * 132 + n0 + 2 * q]      = cvt_tf32(fmaxf(C0[2], 0.0f));
        H[(m0 + 8 + g8) * 132 + n0 + 2 * q + 1]  = cvt_tf32(fmaxf(C0[3], 0.0f));
        H[(m0 + 16 + g8) * 132 + n0 + 2 * q]     = cvt_tf32(fmaxf(C1[0], 0.0f));
        H[(m0 + 16 + g8) * 132 + n0 + 2 * q + 1] = cvt_tf32(fmaxf(C1[1], 0.0f));
        H[(m0 + 24 + g8) * 132 + n0 + 2 * q]     = cvt_tf32(fmaxf(C1[2], 0.0f));
        H[(m0 + 24 + g8) * 132 + n0 + 2 * q + 1] = cvt_tf32(fmaxf(C1[3], 0.0f));
    }
    __syncwarp();

    // ---- layer 1: [128x128] @ [128x128] + fused layer 2 ----
    uint32_t a1f[2][16][4];
#pragma unroll
    for (int t = 0; t < 2; t++) {
        const int r0 = m0 + 16 * t;
#pragma unroll
        for (int kk = 0; kk < 16; kk++) {
            const int k = kk * 8 + q;
            a1f[t][kk][0] = H[(r0 + g8) * 132 + k];
            a1f[t][kk][1] = H[(r0 + 8 + g8) * 132 + k];
            a1f[t][kk][2] = H[(r0 + g8) * 132 + k + 4];
            a1f[t][kk][3] = H[(r0 + 8 + g8) * 132 + k + 4];
        }
    }

    float acc[4][3];
#pragma unroll
    for (int i = 0; i < 4; i++)
#pragma unroll
        for (int c = 0; c < 3; c++) acc[i][c] = 0.0f;

    const float* W2s = sm + SM_W2;
    for (int nt = 0; nt < 16; nt++) {
        const int n0 = nt * 8;
        const float cb0 = sm[SM_B1 + n0 + 2 * q];
        const float cb1 = sm[SM_B1 + n0 + 2 * q + 1];
        float C0[4] = {cb0, cb1, cb0, cb1};
        float C1[4] = {cb0, cb1, cb0, cb1};
#pragma unroll
        for (int kk = 0; kk < 16; kk++) {
            const int k = kk * 8 + q;
            const uint32_t bb0 = W1T[(n0 + g8) * 132 + k];
            const uint32_t bb1 = W1T[(n0 + g8) * 132 + k + 4];
            mma_tf32(C0, a1f[0][kk][0], a1f[0][kk][1], a1f[0][kk][2], a1f[0][kk][3], bb0, bb1);
            mma_tf32(C1, a1f[1][kk][0], a1f[1][kk][1], a1f[1][kk][2], a1f[1][kk][3], bb0, bb1);
        }
        const int col0 = n0 + 2 * q, col1 = col0 + 1;
        const float w20x = W2s[col0 * 3 + 0], w20y = W2s[col0 * 3 + 1], w20z = W2s[col0 * 3 + 2];
        const float w21x = W2s[col1 * 3 + 0], w21y = W2s[col1 * 3 + 1], w21z = W2s[col1 * 3 + 2];
        {
            const float h0 = fmaxf(C0[0], 0.0f), h1 = fmaxf(C0[1], 0.0f);
            const float h2 = fmaxf(C0[2], 0.0f), h3 = fmaxf(C0[3], 0.0f);
            acc[0][0] += h0 * w20x + h1 * w21x;
            acc[0][1] += h0 * w20y + h1 * w21y;
            acc[0][2] += h0 * w20z + h1 * w21z;
            acc[1][0] += h2 * w20x + h3 * w21x;
            acc[1][1] += h2 * w20y + h3 * w21y;
            acc[1][2] += h2 * w20z + h3 * w21z;
        }
        {
            const float h0 = fmaxf(C1[0], 0.0f), h1 = fmaxf(C1[1], 0.0f);
            const float h2 = fmaxf(C1[2], 0.0f), h3 = fmaxf(C1[3], 0.0f);
            acc[2][0] += h0 * w20x + h1 * w21x;
            acc[2][1] += h0 * w20y + h1 * w21y;
            acc[2][2] += h0 * w20z + h1 * w21z;
            acc[3][0] += h2 * w20x + h3 * w21x;
            acc[3][1] += h2 * w20y + h3 * w21y;
            acc[3][2] += h2 * w20z + h3 * w21z;
        }
    }

    // quad reduction (lanes differing in low 2 bits hold disjoint columns)
#pragma unroll
    for (int i = 0; i < 4; i++)
#pragma unroll
        for (int c = 0; c < 3; c++) {
            acc[i][c] += __shfl_xor_sync(0xFFFFFFFFu, acc[i][c], 1);
            acc[i][c] += __shfl_xor_sync(0xFFFFFFFFu, acc[i][c], 2);
        }

    if (q == 0) {
        const float bb0 = sm[SM_B2 + 0], bb1 = sm[SM_B2 + 1], bb2 = sm[SM_B2 + 2];
        const int rows[4] = {m0 + g8, m0 + 8 + g8, m0 + 16 + g8, m0 + 24 + g8};
#pragma unroll
        for (int i = 0; i < 4; i++) {
            const int oidx = blockIdx.x * 128 + rows[i];
            g_rgb0[oidx] = 1.0f / (1.0f + __expf(-(acc[i][0] + bb0)));
            g_rgb1[oidx] = 1.0f / (1.0f + __expf(-(acc[i][1] + bb1)));
            g_rgb2[oidx] = 1.0f / (1.0f + __expf(-(acc[i][2] + bb2)));
        }
    }
}

// ---------------- compositing: one warp per ray ----------------
__global__ void __launch_bounds__(256)
composite_kernel(float* __restrict__ out)
{
    const int gwarp = (blockIdx.x * blockDim.x + threadIdx.x) >> 5;
    const int lane = threadIdx.x & 31;
    if (gwarp >= N_RAYS) return;
    const int r = gwarp;

    float T = 1.0f, wsum = 0.0f, a0 = 0.0f, a1 = 0.0f, a2 = 0.0f;
#pragma unroll
    for (int chunk = 0; chunk < N_SAMPLES / 32; chunk++) {
        const int off = r * N_SAMPLES + chunk * 32 + lane;
        const float alpha = g_alpha[off];
        const float c0 = g_rgb0[off];
        const float c1 = g_rgb1[off];
        const float c2 = g_rgb2[off];
        float p = 1.0f - alpha + 1e-10f;
#pragma unroll
        for (int d = 1; d < 32; d <<= 1) {
            const float up = __shfl_up_sync(0xFFFFFFFFu, p, d);
            if (lane >= d) p *= up;
        }
        float excl = __shfl_up_sync(0xFFFFFFFFu, p, 1);
        if (lane == 0) excl = 1.0f;
        const float w = alpha * T * excl;
        wsum += w;
        a0 += w * c0; a1 += w * c1; a2 += w * c2;
        T *= __shfl_sync(0xFFFFFFFFu, p, 31);
    }
#pragma unroll
    for (int d = 16; d > 0; d >>= 1) {
        wsum += __shfl_down_sync(0xFFFFFFFFu, wsum, d);
        a0 += __shfl_down_sync(0xFFFFFFFFu, a0, d);
        a1 += __shfl_down_sync(0xFFFFFFFFu, a1, d);
        a2 += __shfl_down_sync(0xFFFFFFFFu, a2, d);
    }
    if (lane == 0) {
        const float bg = 1.0f - wsum;
        out[r * 3 + 0] = a0 + bg;
        out[r * 3 + 1] = a1 + bg;
        out[r * 3 + 2] = a2 + bg;
    }
}

extern "C" void kernel_launch(void* const* d_in, const int* in_sizes, int n_in,
                              void* d_out, int out_size)
{
    const float* rays_o = (const float*)d_in[0];
    const float* rays_d = (const float*)d_in[1];
    const float* dgrid  = (const float*)d_in[2];
    const float* k0grid = (const float*)d_in[3];
    const float* w0 = (const float*)d_in[4];
    const float* b0 = (const float*)d_in[5];
    const float* w1 = (const float*)d_in[6];
    const float* b1 = (const float*)d_in[7];
    const float* w2 = (const float*)d_in[8];
    const float* b2 = (const float*)d_in[9];
    float* out = (float*)d_out;

    cudaFuncSetAttribute(point_kernel,
                         cudaFuncAttributeMaxDynamicSharedMemorySize, SMEM_BYTES);

    prep_kernel<<<48, 256>>>(w0, w1);
    point_kernel<<<NPTS / 128, 128, SMEM_BYTES>>>(rays_o, rays_d, dgrid, k0grid,
                                                  w2, b0, b1, b2);
    composite_kernel<<<(N_RAYS * 32 + 255) / 256, 256>>>(out);
}

// round 7
// speedup vs baseline: 3.1815x; 1.1823x over previous
#include <cuda_runtime.h>
#include <cstdint>
#include <math.h>

#define N_RAYS 4096
#define N_SAMPLES 192
#define GRID_D 160
#define GRID_D2 (160*160)
#define GRID_D3 (160*160*160)
#define K0_DIM 12
#define XYZ_MIN (-1.2f)
#define COORD_SCALE (159.0f / 2.4f)
#define ACT_SHIFT (-4.595119850134589f)
#define STEPDIST (2.8f / 192.0f)
#define NEARV 0.2f
#define FARV 3.0f

#define NPTS (N_RAYS * N_SAMPLES)

// ---------------- scratch ----------------
__device__ float g_alpha[NPTS];
__device__ float g_rgb0[NPTS];
__device__ float g_rgb1[NPTS];
__device__ float g_rgb2[NPTS];
// prepacked transposed bf16x2 weights, padded strides for conflict-free LDS
__device__ uint32_t PW0T[128 * 28];   // [n][kpair], k<39 real (pad to 48+8)
__device__ uint32_t PW1T[128 * 68];   // [n][kpair], k<128 real (pad stride 136)

// ---------------- smem layout (4-byte word units) ----------------
#define SM_W0T 0                       /* 128*28 = 3584 */
#define SM_W1T 3584                    /* 128*68 = 8704 */
#define SM_F   (SM_W1T + 8704)         /* 128*28 = 3584 */
#define SM_H   (SM_F + 3584)           /* 128*68 = 8704 */
#define SM_W2  (SM_H + 8704)           /* 384 */
#define SM_B0  (SM_W2 + 384)
#define SM_B1  (SM_B0 + 128)
#define SM_B2  (SM_B1 + 128)
#define SM_WORDS (SM_B2 + 4)
#define SMEM_BYTES (SM_WORDS * 4)      /* ~100.9 KB -> 2 CTAs/SM */

__device__ __forceinline__ uint32_t pack_bf16x2(float lo, float hi) {
    uint32_t u;
    asm("cvt.rn.bf16x2.f32 %0, %1, %2;" : "=r"(u) : "f"(hi), "f"(lo));
    return u;
}

__device__ __forceinline__ void mma_bf16(float c[4],
                                         uint32_t a0, uint32_t a1, uint32_t a2, uint32_t a3,
                                         uint32_t b0, uint32_t b1) {
    asm volatile("mma.sync.aligned.m16n8k16.row.col.f32.bf16.bf16.f32 "
                 "{%0,%1,%2,%3}, {%4,%5,%6,%7}, {%8,%9}, {%0,%1,%2,%3};"
                 : "+f"(c[0]), "+f"(c[1]), "+f"(c[2]), "+f"(c[3])
                 : "r"(a0), "r"(a1), "r"(a2), "r"(a3), "r"(b0), "r"(b1));
}

// ---------------- prep: pack W0^T / W1^T bf16x2, padded ----------------
__global__ void prep_kernel(const float* __restrict__ w0, const float* __restrict__ w1)
{
    const int t = blockIdx.x * blockDim.x + threadIdx.x;
    const int stride = gridDim.x * blockDim.x;
    for (int i = t; i < 128 * 28; i += stride) {
        const int n = i / 28, wd = i - n * 28;
        const int k = 2 * wd;
        const float lo = (k < 39) ? w0[k * 128 + n] : 0.0f;
        const float hi = (k + 1 < 39) ? w0[(k + 1) * 128 + n] : 0.0f;
        PW0T[i] = pack_bf16x2(lo, hi);
    }
    for (int i = t; i < 128 * 68; i += stride) {
        const int n = i / 68, wd = i - n * 68;
        const int k = 2 * wd;
        const float lo = (k < 128) ? w1[k * 128 + n] : 0.0f;
        const float hi = (k + 1 < 128) ? w1[(k + 1) * 128 + n] : 0.0f;
        PW1T[i] = pack_bf16x2(lo, hi);
    }
}

// ---------------- point kernel: 128 samples / block, 2 CTAs/SM ----------------
__global__ void __launch_bounds__(128, 2)
point_kernel(const float* __restrict__ rays_o,
             const float* __restrict__ rays_d,
             const float* __restrict__ dgrid,
             const float* __restrict__ k0grid,
             const float* __restrict__ w2,
             const float* __restrict__ b0,
             const float* __restrict__ b1,
             const float* __restrict__ b2)
{
    extern __shared__ float sm[];
    uint32_t* smw = (uint32_t*)sm;
    const int tid = threadIdx.x;

    // ---- stage prepacked weights (coalesced; completes at syncthreads) ----
    {
        float4* d0 = (float4*)(smw + SM_W0T);
        const float4* s0 = (const float4*)PW0T;
        for (int i = tid; i < 896; i += 128) d0[i] = s0[i];
        float4* d1 = (float4*)(smw + SM_W1T);
        const float4* s1 = (const float4*)PW1T;
        for (int i = tid; i < 2176; i += 128) d1[i] = s1[i];
    }
    for (int i = tid; i < 384; i += 128) sm[SM_W2 + i] = w2[i];
    sm[SM_B0 + tid] = b0[tid];
    sm[SM_B1 + tid] = b1[tid];
    if (tid < 3) sm[SM_B2 + tid] = b2[tid];

    // ---- per-sample point / trilerp / features ----
    const int idx = blockIdx.x * 128 + tid;
    const int r = idx / N_SAMPLES;
    const int s = idx - r * N_SAMPLES;

    float dx = rays_d[r * 3 + 0], dy = rays_d[r * 3 + 1], dz = rays_d[r * 3 + 2];
    const float inv = rsqrtf(dx * dx + dy * dy + dz * dz);
    const float vx = dx * inv, vy = dy * inv, vz = dz * inv;
    const float tval = NEARV + (FARV - NEARV) * ((float)s + 0.5f) / (float)N_SAMPLES;
    float px = rays_o[r * 3 + 0] + vx * tval;
    float py = rays_o[r * 3 + 1] + vy * tval;
    float pz = rays_o[r * 3 + 2] + vz * tval;
    const float nrm = fmaxf(fabsf(px), fmaxf(fabsf(py), fabsf(pz)));
    if (nrm > 1.0f) {
        const float invn = 1.0f / nrm;
        const float sc = (1.2f - 0.2f * invn) * invn;
        px *= sc; py *= sc; pz *= sc;
    }
    float gx = (px - XYZ_MIN) * COORD_SCALE;
    float gy = (py - XYZ_MIN) * COORD_SCALE;
    float gz = (pz - XYZ_MIN) * COORD_SCALE;
    gx = fminf(fmaxf(gx, 0.0f), 159.0f);
    gy = fminf(fmaxf(gy, 0.0f), 159.0f);
    gz = fminf(fmaxf(gz, 0.0f), 159.0f);
    const int ix = min((int)floorf(gx), 158);
    const int iy = min((int)floorf(gy), 158);
    const int iz = min((int)floorf(gz), 158);
    const float fx = gx - (float)ix, fy = gy - (float)iy, fz = gz - (float)iz;
    const float ex = 1.0f - fx, ey = 1.0f - fy, ez = 1.0f - fz;
    const int base = ix * GRID_D2 + iy * GRID_D + iz;
    const float w000 = ex * ey * ez, w100 = fx * ey * ez;
    const float w010 = ex * fy * ez, w001 = ex * ey * fz;
    const float w110 = fx * fy * ez, w101 = fx * ey * fz;
    const float w011 = ex * fy * fz, w111 = fx * fy * fz;

    {
        const float* g = dgrid + base;
        const float dv = g[0] * w000 + g[GRID_D2] * w100 + g[GRID_D] * w010 + g[1] * w001
                       + g[GRID_D2 + GRID_D] * w110 + g[GRID_D2 + 1] * w101
                       + g[GRID_D + 1] * w011 + g[GRID_D2 + GRID_D + 1] * w111;
        const float x = dv + ACT_SHIFT;
        const float sigma = fmaxf(x, 0.0f) + log1pf(__expf(-fabsf(x)));
        g_alpha[idx] = 1.0f - __expf(-sigma * STEPDIST);
    }

    float feat[48];
#pragma unroll
    for (int c = 0; c < K0_DIM; c++) {
        const float* g = k0grid + c * GRID_D3 + base;
        feat[c] = g[0] * w000 + g[GRID_D2] * w100 + g[GRID_D] * w010 + g[1] * w001
                + g[GRID_D2 + GRID_D] * w110 + g[GRID_D2 + 1] * w101
                + g[GRID_D + 1] * w011 + g[GRID_D2 + GRID_D + 1] * w111;
    }
    feat[12] = vx; feat[13] = vy; feat[14] = vz;
    {
        const float v3[3] = {vx, vy, vz};
#pragma unroll
        for (int i = 0; i < 3; i++) {
#pragma unroll
            for (int p = 0; p < 4; p++) {
                float sv, cv;
                __sincosf(v3[i] * (float)(1 << p), &sv, &cv);
                feat[15 + i * 4 + p] = sv;
                feat[27 + i * 4 + p] = cv;
            }
        }
    }
#pragma unroll
    for (int j = 39; j < 48; j++) feat[j] = 0.0f;

    // feature row -> smem bf16x2, row = tid, stride 28 words (56 bf16)
    {
        uint32_t* F = smw + SM_F;
#pragma unroll
        for (int j = 0; j < 24; j++)
            F[tid * 28 + j] = pack_bf16x2(feat[2 * j], feat[2 * j + 1]);
    }

    __syncthreads();

    const int lane = tid & 31;
    const int warp = tid >> 5;
    const int g8 = lane >> 2;      // groupID 0..7
    const int q = lane & 3;        // threadID_in_group
    const int m0 = warp * 32;

    const uint32_t* F   = smw + SM_F;
    const uint32_t* W0T = smw + SM_W0T;
    const uint32_t* W1T = smw + SM_W1T;
    uint32_t* H = smw + SM_H;

    // ---- layer 0: [128x48] @ [48x128] bf16 (3 k-steps) ----
    uint32_t af[2][3][4];
#pragma unroll
    for (int t = 0; t < 2; t++) {
        const int r0 = m0 + 16 * t;
#pragma unroll
        for (int kk = 0; kk < 3; kk++) {
            const int w = kk * 8 + q;
            af[t][kk][0] = F[(r0 + g8) * 28 + w];
            af[t][kk][1] = F[(r0 + 8 + g8) * 28 + w];
            af[t][kk][2] = F[(r0 + g8) * 28 + w + 4];
            af[t][kk][3] = F[(r0 + 8 + g8) * 28 + w + 4];
        }
    }
#pragma unroll
    for (int nt = 0; nt < 16; nt++) {
        const int n0 = nt * 8;
        const float cb0 = sm[SM_B0 + n0 + 2 * q];
        const float cb1 = sm[SM_B0 + n0 + 2 * q + 1];
        float C0[4] = {cb0, cb1, cb0, cb1};
        float C1[4] = {cb0, cb1, cb0, cb1};
#pragma unroll
        for (int kk = 0; kk < 3; kk++) {
            const int w = kk * 8 + q;
            const uint32_t bb0 = W0T[(n0 + g8) * 28 + w];
            const uint32_t bb1 = W0T[(n0 + g8) * 28 + w + 4];
            mma_bf16(C0, af[0][kk][0], af[0][kk][1], af[0][kk][2], af[0][kk][3], bb0, bb1);
            mma_bf16(C1, af[1][kk][0], af[1][kk][1], af[1][kk][2], af[1][kk][3], bb0, bb1);
        }
        // relu -> bf16x2 -> H (stride 68 words), rows are warp-private
        const int hc = (n0 >> 1) + q;
        H[(m0 + g8) * 68 + hc]      = pack_bf16x2(fmaxf(C0[0], 0.0f), fmaxf(C0[1], 0.0f));
        H[(m0 + 8 + g8) * 68 + hc]  = pack_bf16x2(fmaxf(C0[2], 0.0f), fmaxf(C0[3], 0.0f));
        H[(m0 + 16 + g8) * 68 + hc] = pack_bf16x2(fmaxf(C1[0], 0.0f), fmaxf(C1[1], 0.0f));
        H[(m0 + 24 + g8) * 68 + hc] = pack_bf16x2(fmaxf(C1[2], 0.0f), fmaxf(C1[3], 0.0f));
    }
    __syncwarp();

    // ---- layer 1: [128x128] @ [128x128] bf16 (8 k-steps) + fused layer 2 ----
    uint32_t a1f[2][8][4];
#pragma unroll
    for (int t = 0; t < 2; t++) {
        const int r0 = m0 + 16 * t;
#pragma unroll
        for (int kk = 0; kk < 8; kk++) {
            const int w = kk * 8 + q;
            a1f[t][kk][0] = H[(r0 + g8) * 68 + w];
            a1f[t][kk][1] = H[(r0 + 8 + g8) * 68 + w];
            a1f[t][kk][2] = H[(r0 + g8) * 68 + w + 4];
            a1f[t][kk][3] = H[(r0 + 8 + g8) * 68 + w + 4];
        }
    }

    float acc[4][3];
#pragma unroll
    for (int i = 0; i < 4; i++)
#pragma unroll
        for (int c = 0; c < 3; c++) acc[i][c] = 0.0f;

    const float* W2s = sm + SM_W2;
#pragma unroll
    for (int nt = 0; nt < 16; nt++) {
        const int n0 = nt * 8;
        const float cb0 = sm[SM_B1 + n0 + 2 * q];
        const float cb1 = sm[SM_B1 + n0 + 2 * q + 1];
        float C0[4] = {cb0, cb1, cb0, cb1};
        float C1[4] = {cb0, cb1, cb0, cb1};
#pragma unroll
        for (int kk = 0; kk < 8; kk++) {
            const int w = kk * 8 + q;
            const uint32_t bb0 = W1T[(n0 + g8) * 68 + w];
            const uint32_t bb1 = W1T[(n0 + g8) * 68 + w + 4];
            mma_bf16(C0, a1f[0][kk][0], a1f[0][kk][1], a1f[0][kk][2], a1f[0][kk][3], bb0, bb1);
            mma_bf16(C1, a1f[1][kk][0], a1f[1][kk][1], a1f[1][kk][2], a1f[1][kk][3], bb0, bb1);
        }
        const int col0 = n0 + 2 * q, col1 = col0 + 1;
        const float w20x = W2s[col0 * 3 + 0], w20y = W2s[col0 * 3 + 1], w20z = W2s[col0 * 3 + 2];
        const float w21x = W2s[col1 * 3 + 0], w21y = W2s[col1 * 3 + 1], w21z = W2s[col1 * 3 + 2];
        {
            const float h0 = fmaxf(C0[0], 0.0f), h1 = fmaxf(C0[1], 0.0f);
            const float h2 = fmaxf(C0[2], 0.0f), h3 = fmaxf(C0[3], 0.0f);
            acc[0][0] += h0 * w20x + h1 * w21x;
            acc[0][1] += h0 * w20y + h1 * w21y;
            acc[0][2] += h0 * w20z + h1 * w21z;
            acc[1][0] += h2 * w20x + h3 * w21x;
            acc[1][1] += h2 * w20y + h3 * w21y;
            acc[1][2] += h2 * w20z + h3 * w21z;
        }
        {
            const float h0 = fmaxf(C1[0], 0.0f), h1 = fmaxf(C1[1], 0.0f);
            const float h2 = fmaxf(C1[2], 0.0f), h3 = fmaxf(C1[3], 0.0f);
            acc[2][0] += h0 * w20x + h1 * w21x;
            acc[2][1] += h0 * w20y + h1 * w21y;
            acc[2][2] += h0 * w20z + h1 * w21z;
            acc[3][0] += h2 * w20x + h3 * w21x;
            acc[3][1] += h2 * w20y + h3 * w21y;
            acc[3][2] += h2 * w20z + h3 * w21z;
        }
    }

    // quad reduction (lanes differing in low 2 bits hold disjoint columns)
#pragma unroll
    for (int i = 0; i < 4; i++)
#pragma unroll
        for (int c = 0; c < 3; c++) {
            acc[i][c] += __shfl_xor_sync(0xFFFFFFFFu, acc[i][c], 1);
            acc[i][c] += __shfl_xor_sync(0xFFFFFFFFu, acc[i][c], 2);
        }

    if (q == 0) {
        const float bb0 = sm[SM_B2 + 0], bb1 = sm[SM_B2 + 1], bb2 = sm[SM_B2 + 2];
        const int rows[4] = {m0 + g8, m0 + 8 + g8, m0 + 16 + g8, m0 + 24 + g8};
#pragma unroll
        for (int i = 0; i < 4; i++) {
            const int oidx = blockIdx.x * 128 + rows[i];
            g_rgb0[oidx] = 1.0f / (1.0f + __expf(-(acc[i][0] + bb0)));
            g_rgb1[oidx] = 1.0f / (1.0f + __expf(-(acc[i][1] + bb1)));
            g_rgb2[oidx] = 1.0f / (1.0f + __expf(-(acc[i][2] + bb2)));
        }
    }
}

// ---------------- compositing: one warp per ray ----------------
__global__ void __launch_bounds__(256)
composite_kernel(float* __restrict__ out)
{
    const int gwarp = (blockIdx.x * blockDim.x + threadIdx.x) >> 5;
    const int lane = threadIdx.x & 31;
    if (gwarp >= N_RAYS) return;
    const int r = gwarp;

    float T = 1.0f, wsum = 0.0f, a0 = 0.0f, a1 = 0.0f, a2 = 0.0f;
#pragma unroll
    for (int chunk = 0; chunk < N_SAMPLES / 32; chunk++) {
        const int off = r * N_SAMPLES + chunk * 32 + lane;
        const float alpha = g_alpha[off];
        const float c0 = g_rgb0[off];
        const float c1 = g_rgb1[off];
        const float c2 = g_rgb2[off];
        float p = 1.0f - alpha + 1e-10f;
#pragma unroll
        for (int d = 1; d < 32; d <<= 1) {
            const float up = __shfl_up_sync(0xFFFFFFFFu, p, d);
            if (lane >= d) p *= up;
        }
        float excl = __shfl_up_sync(0xFFFFFFFFu, p, 1);
        if (lane == 0) excl = 1.0f;
        const float w = alpha * T * excl;
        wsum += w;
        a0 += w * c0; a1 += w * c1; a2 += w * c2;
        T *= __shfl_sync(0xFFFFFFFFu, p, 31);
    }
#pragma unroll
    for (int d = 16; d > 0; d >>= 1) {
        wsum += __shfl_down_sync(0xFFFFFFFFu, wsum, d);
        a0 += __shfl_down_sync(0xFFFFFFFFu, a0, d);
        a1 += __shfl_down_sync(0xFFFFFFFFu, a1, d);
        a2 += __shfl_down_sync(0xFFFFFFFFu, a2, d);
    }
    if (lane == 0) {
        const float bg = 1.0f - wsum;
        out[r * 3 + 0] = a0 + bg;
        out[r * 3 + 1] = a1 + bg;
        out[r * 3 + 2] = a2 + bg;
    }
}

extern "C" void kernel_launch(void* const* d_in, const int* in_sizes, int n_in,
                              void* d_out, int out_size)
{
    const float* rays_o = (const float*)d_in[0];
    const float* rays_d = (const float*)d_in[1];
    const float* dgrid  = (const float*)d_in[2];
    const float* k0grid = (const float*)d_in[3];
    const float* w0 = (const float*)d_in[4];
    const float* b0 = (const float*)d_in[5];
    const float* w1 = (const float*)d_in[6];
    const float* b1 = (const float*)d_in[7];
    const float* w2 = (const float*)d_in[8];
    const float* b2 = (const float*)d_in[9];
    float* out = (float*)d_out;

    cudaFuncSetAttribute(point_kernel,
                         cudaFuncAttributeMaxDynamicSharedMemorySize, SMEM_BYTES);

    prep_kernel<<<48, 256>>>(w0, w1);
    point_kernel<<<NPTS / 128, 128, SMEM_BYTES>>>(rays_o, rays_d, dgrid, k0grid,
                                                  w2, b0, b1, b2);
    composite_kernel<<<(N_RAYS * 32 + 255) / 256, 256>>>(out);
}

// round 8
// speedup vs baseline: 3.5437x; 1.1138x over previous
#include <cuda_runtime.h>
#include <cstdint>
#include <math.h>

#define N_RAYS 4096
#define N_SAMPLES 192
#define GRID_D 160
#define GRID_D2 (160*160)
#define GRID_D3 (160*160*160)
#define K0_DIM 12
#define XYZ_MIN (-1.2f)
#define COORD_SCALE (159.0f / 2.4f)
#define ACT_SHIFT (-4.595119850134589f)
#define STEPDIST (2.8f / 192.0f)
#define NEARV 0.2f
#define FARV 3.0f

#define NPTS (N_RAYS * N_SAMPLES)

// ---------------- scratch ----------------
__device__ float g_alpha[NPTS];
__device__ float g_rgb0[NPTS];
__device__ float g_rgb1[NPTS];
__device__ float g_rgb2[NPTS];
// prepacked transposed bf16x2 weights, padded strides for conflict-free LDS
__device__ uint32_t PW0T[128 * 28];   // [n][kpair], k<39 real (pad to 48)
__device__ uint32_t PW1T[128 * 68];   // [n][kpair], k<128 real

// ---------------- smem layout (4-byte word units) ----------------
#define SM_W0T 0                       /* 128*28 = 3584 */
#define SM_W1T 3584                    /* 128*68 = 8704 */
#define SM_F   (SM_W1T + 8704)         /* 128*28 = 3584 */
#define SM_W2  (SM_F + 3584)           /* 384 */
#define SM_B0  (SM_W2 + 384)
#define SM_B1  (SM_B0 + 128)
#define SM_B2  (SM_B1 + 128)
#define SM_WORDS (SM_B2 + 4)
#define SMEM_BYTES (SM_WORDS * 4)      /* ~64.5 KB -> 3 CTAs/SM */

__device__ __forceinline__ uint32_t pack_bf16x2(float lo, float hi) {
    uint32_t u;
    asm("cvt.rn.bf16x2.f32 %0, %1, %2;" : "=r"(u) : "f"(hi), "f"(lo));
    return u;
}

__device__ __forceinline__ void mma_bf16(float c[4],
                                         uint32_t a0, uint32_t a1, uint32_t a2, uint32_t a3,
                                         uint32_t b0, uint32_t b1) {
    asm volatile("mma.sync.aligned.m16n8k16.row.col.f32.bf16.bf16.f32 "
                 "{%0,%1,%2,%3}, {%4,%5,%6,%7}, {%8,%9}, {%0,%1,%2,%3};"
                 : "+f"(c[0]), "+f"(c[1]), "+f"(c[2]), "+f"(c[3])
                 : "r"(a0), "r"(a1), "r"(a2), "r"(a3), "r"(b0), "r"(b1));
}

// ---------------- prep: pack W0^T / W1^T bf16x2, padded ----------------
__global__ void prep_kernel(const float* __restrict__ w0, const float* __restrict__ w1)
{
    const int t = blockIdx.x * blockDim.x + threadIdx.x;
    const int stride = gridDim.x * blockDim.x;
    for (int i = t; i < 128 * 28; i += stride) {
        const int n = i / 28, wd = i - n * 28;
        const int k = 2 * wd;
        const float lo = (k < 39) ? w0[k * 128 + n] : 0.0f;
        const float hi = (k + 1 < 39) ? w0[(k + 1) * 128 + n] : 0.0f;
        PW0T[i] = pack_bf16x2(lo, hi);
    }
    for (int i = t; i < 128 * 68; i += stride) {
        const int n = i / 68, wd = i - n * 68;
        const int k = 2 * wd;
        const float lo = (k < 128) ? w1[k * 128 + n] : 0.0f;
        const float hi = (k + 1 < 128) ? w1[(k + 1) * 128 + n] : 0.0f;
        PW1T[i] = pack_bf16x2(lo, hi);
    }
}

// ---------------- point kernel: 128 samples / block, 3 CTAs/SM ----------------
__global__ void __launch_bounds__(128, 3)
point_kernel(const float* __restrict__ rays_o,
             const float* __restrict__ rays_d,
             const float* __restrict__ dgrid,
             const float* __restrict__ k0grid,
             const float* __restrict__ w2,
             const float* __restrict__ b0,
             const float* __restrict__ b1,
             const float* __restrict__ b2)
{
    extern __shared__ float sm[];
    uint32_t* smw = (uint32_t*)sm;
    const int tid = threadIdx.x;

    // ---- stage prepacked weights (coalesced; completes at syncthreads) ----
    {
        float4* d0 = (float4*)(smw + SM_W0T);
        const float4* s0 = (const float4*)PW0T;
        for (int i = tid; i < 896; i += 128) d0[i] = s0[i];
        float4* d1 = (float4*)(smw + SM_W1T);
        const float4* s1 = (const float4*)PW1T;
        for (int i = tid; i < 2176; i += 128) d1[i] = s1[i];
    }
    for (int i = tid; i < 384; i += 128) sm[SM_W2 + i] = w2[i];
    sm[SM_B0 + tid] = b0[tid];
    sm[SM_B1 + tid] = b1[tid];
    if (tid < 3) sm[SM_B2 + tid] = b2[tid];

    // ---- per-sample point / trilerp / features ----
    const int idx = blockIdx.x * 128 + tid;
    const int r = idx / N_SAMPLES;
    const int s = idx - r * N_SAMPLES;

    float dx = rays_d[r * 3 + 0], dy = rays_d[r * 3 + 1], dz = rays_d[r * 3 + 2];
    const float inv = rsqrtf(dx * dx + dy * dy + dz * dz);
    const float vx = dx * inv, vy = dy * inv, vz = dz * inv;
    const float tval = NEARV + (FARV - NEARV) * ((float)s + 0.5f) / (float)N_SAMPLES;
    float px = rays_o[r * 3 + 0] + vx * tval;
    float py = rays_o[r * 3 + 1] + vy * tval;
    float pz = rays_o[r * 3 + 2] + vz * tval;
    const float nrm = fmaxf(fabsf(px), fmaxf(fabsf(py), fabsf(pz)));
    if (nrm > 1.0f) {
        const float invn = 1.0f / nrm;
        const float sc = (1.2f - 0.2f * invn) * invn;
        px *= sc; py *= sc; pz *= sc;
    }
    float gx = (px - XYZ_MIN) * COORD_SCALE;
    float gy = (py - XYZ_MIN) * COORD_SCALE;
    float gz = (pz - XYZ_MIN) * COORD_SCALE;
    gx = fminf(fmaxf(gx, 0.0f), 159.0f);
    gy = fminf(fmaxf(gy, 0.0f), 159.0f);
    gz = fminf(fmaxf(gz, 0.0f), 159.0f);
    const int ix = min((int)floorf(gx), 158);
    const int iy = min((int)floorf(gy), 158);
    const int iz = min((int)floorf(gz), 158);
    const float fx = gx - (float)ix, fy = gy - (float)iy, fz = gz - (float)iz;
    const float ex = 1.0f - fx, ey = 1.0f - fy, ez = 1.0f - fz;
    const int base = ix * GRID_D2 + iy * GRID_D + iz;
    const float w000 = ex * ey * ez, w100 = fx * ey * ez;
    const float w010 = ex * fy * ez, w001 = ex * ey * fz;
    const float w110 = fx * fy * ez, w101 = fx * ey * fz;
    const float w011 = ex * fy * fz, w111 = fx * fy * fz;

    {
        const float* g = dgrid + base;
        const float dv = g[0] * w000 + g[GRID_D2] * w100 + g[GRID_D] * w010 + g[1] * w001
                       + g[GRID_D2 + GRID_D] * w110 + g[GRID_D2 + 1] * w101
                       + g[GRID_D + 1] * w011 + g[GRID_D2 + GRID_D + 1] * w111;
        const float x = dv + ACT_SHIFT;
        const float sigma = fmaxf(x, 0.0f) + log1pf(__expf(-fabsf(x)));
        g_alpha[idx] = 1.0f - __expf(-sigma * STEPDIST);
    }

    float feat[48];
#pragma unroll
    for (int c = 0; c < K0_DIM; c++) {
        const float* g = k0grid + c * GRID_D3 + base;
        feat[c] = g[0] * w000 + g[GRID_D2] * w100 + g[GRID_D] * w010 + g[1] * w001
                + g[GRID_D2 + GRID_D] * w110 + g[GRID_D2 + 1] * w101
                + g[GRID_D + 1] * w011 + g[GRID_D2 + GRID_D + 1] * w111;
    }
    feat[12] = vx; feat[13] = vy; feat[14] = vz;
    {
        const float v3[3] = {vx, vy, vz};
#pragma unroll
        for (int i = 0; i < 3; i++) {
#pragma unroll
            for (int p = 0; p < 4; p++) {
                float sv, cv;
                __sincosf(v3[i] * (float)(1 << p), &sv, &cv);
                feat[15 + i * 4 + p] = sv;
                feat[27 + i * 4 + p] = cv;
            }
        }
    }
#pragma unroll
    for (int j = 39; j < 48; j++) feat[j] = 0.0f;

    // feature row -> smem bf16x2, row = tid, stride 28 words (56 bf16)
    {
        uint32_t* F = smw + SM_F;
#pragma unroll
        for (int j = 0; j < 24; j++)
            F[tid * 28 + j] = pack_bf16x2(feat[2 * j], feat[2 * j + 1]);
    }

    __syncthreads();   // weights staged; F rows are warp-private but barrier is shared

    const int lane = tid & 31;
    const int warp = tid >> 5;
    const int g8 = lane >> 2;      // groupID 0..7
    const int q = lane & 3;        // threadID_in_group
    const int m0 = warp * 32;

    const uint32_t* F   = smw + SM_F;
    const uint32_t* W0T = smw + SM_W0T;
    const uint32_t* W1T = smw + SM_W1T;

    // ---- layer 0: [128x48] @ [48x128] bf16 (3 k-steps) ----
    uint32_t af[2][3][4];
#pragma unroll
    for (int t = 0; t < 2; t++) {
        const int r0 = m0 + 16 * t;
#pragma unroll
        for (int kk = 0; kk < 3; kk++) {
            const int w = kk * 8 + q;
            af[t][kk][0] = F[(r0 + g8) * 28 + w];
            af[t][kk][1] = F[(r0 + 8 + g8) * 28 + w];
            af[t][kk][2] = F[(r0 + g8) * 28 + w + 4];
            af[t][kk][3] = F[(r0 + 8 + g8) * 28 + w + 4];
        }
    }

    // layer-0 C fragments convert DIRECTLY to layer-1 A fragments in registers:
    // n-tile nt=2kk supplies a0/a1 (k=16kk+2q), nt=2kk+1 supplies a2/a3 (k=16kk+8+2q).
    uint32_t a1f[2][8][4];
#pragma unroll
    for (int nt = 0; nt < 16; nt++) {
        const int n0 = nt * 8;
        const float cb0 = sm[SM_B0 + n0 + 2 * q];
        const float cb1 = sm[SM_B0 + n0 + 2 * q + 1];
        float C0[4] = {cb0, cb1, cb0, cb1};
        float C1[4] = {cb0, cb1, cb0, cb1};
#pragma unroll
        for (int kk = 0; kk < 3; kk++) {
            const int w = kk * 8 + q;
            const uint32_t bb0 = W0T[(n0 + g8) * 28 + w];
            const uint32_t bb1 = W0T[(n0 + g8) * 28 + w + 4];
            mma_bf16(C0, af[0][kk][0], af[0][kk][1], af[0][kk][2], af[0][kk][3], bb0, bb1);
            mma_bf16(C1, af[1][kk][0], af[1][kk][1], af[1][kk][2], af[1][kk][3], bb0, bb1);
        }
        const int kk1 = nt >> 1;
        const int hi = (nt & 1) << 1;   // 0 -> regs a0/a1, 1 -> regs a2/a3
        a1f[0][kk1][hi]     = pack_bf16x2(fmaxf(C0[0], 0.0f), fmaxf(C0[1], 0.0f));
        a1f[0][kk1][hi + 1] = pack_bf16x2(fmaxf(C0[2], 0.0f), fmaxf(C0[3], 0.0f));
        a1f[1][kk1][hi]     = pack_bf16x2(fmaxf(C1[0], 0.0f), fmaxf(C1[1], 0.0f));
        a1f[1][kk1][hi + 1] = pack_bf16x2(fmaxf(C1[2], 0.0f), fmaxf(C1[3], 0.0f));
    }

    // ---- layer 1: [128x128] @ [128x128] bf16 (8 k-steps) + fused layer 2 ----
    float acc[4][3];
#pragma unroll
    for (int i = 0; i < 4; i++)
#pragma unroll
        for (int c = 0; c < 3; c++) acc[i][c] = 0.0f;

    const float* W2s = sm + SM_W2;
#pragma unroll
    for (int nt = 0; nt < 16; nt++) {
        const int n0 = nt * 8;
        const float cb0 = sm[SM_B1 + n0 + 2 * q];
        const float cb1 = sm[SM_B1 + n0 + 2 * q + 1];
        float C0[4] = {cb0, cb1, cb0, cb1};
        float C1[4] = {cb0, cb1, cb0, cb1};
#pragma unroll
        for (int kk = 0; kk < 8; kk++) {
            const int w = kk * 8 + q;
            const uint32_t bb0 = W1T[(n0 + g8) * 68 + w];
            const uint32_t bb1 = W1T[(n0 + g8) * 68 + w + 4];
            mma_bf16(C0, a1f[0][kk][0], a1f[0][kk][1], a1f[0][kk][2], a1f[0][kk][3], bb0, bb1);
            mma_bf16(C1, a1f[1][kk][0], a1f[1][kk][1], a1f[1][kk][2], a1f[1][kk][3], bb0, bb1);
        }
        const int col0 = n0 + 2 * q, col1 = col0 + 1;
        const float w20x = W2s[col0 * 3 + 0], w20y = W2s[col0 * 3 + 1], w20z = W2s[col0 * 3 + 2];
        const float w21x = W2s[col1 * 3 + 0], w21y = W2s[col1 * 3 + 1], w21z = W2s[col1 * 3 + 2];
        {
            const float h0 = fmaxf(C0[0], 0.0f), h1 = fmaxf(C0[1], 0.0f);
            const float h2 = fmaxf(C0[2], 0.0f), h3 = fmaxf(C0[3], 0.0f);
            acc[0][0] += h0 * w20x + h1 * w21x;
            acc[0][1] += h0 * w20y + h1 * w21y;
            acc[0][2] += h0 * w20z + h1 * w21z;
            acc[1][0] += h2 * w20x + h3 * w21x;
            acc[1][1] += h2 * w20y + h3 * w21y;
            acc[1][2] += h2 * w20z + h3 * w21z;
        }
        {
            const float h0 = fmaxf(C1[0], 0.0f), h1 = fmaxf(C1[1], 0.0f);
            const float h2 = fmaxf(C1[2], 0.0f), h3 = fmaxf(C1[3], 0.0f);
            acc[2][0] += h0 * w20x + h1 * w21x;
            acc[2][1] += h0 * w20y + h1 * w21y;
            acc[2][2] += h0 * w20z + h1 * w21z;
            acc[3][0] += h2 * w20x + h3 * w21x;
            acc[3][1] += h2 * w20y + h3 * w21y;
            acc[3][2] += h2 * w20z + h3 * w21z;
        }
    }

    // quad reduction (lanes differing in low 2 bits hold disjoint columns)
#pragma unroll
    for (int i = 0; i < 4; i++)
#pragma unroll
        for (int c = 0; c < 3; c++) {
            acc[i][c] += __shfl_xor_sync(0xFFFFFFFFu, acc[i][c], 1);
            acc[i][c] += __shfl_xor_sync(0xFFFFFFFFu, acc[i][c], 2);
        }

    if (q == 0) {
        const float bb0 = sm[SM_B2 + 0], bb1 = sm[SM_B2 + 1], bb2 = sm[SM_B2 + 2];
        const int rows[4] = {m0 + g8, m0 + 8 + g8, m0 + 16 + g8, m0 + 24 + g8};
#pragma unroll
        for (int i = 0; i < 4; i++) {
            const int oidx = blockIdx.x * 128 + rows[i];
            g_rgb0[oidx] = 1.0f / (1.0f + __expf(-(acc[i][0] + bb0)));
            g_rgb1[oidx] = 1.0f / (1.0f + __expf(-(acc[i][1] + bb1)));
            g_rgb2[oidx] = 1.0f / (1.0f + __expf(-(acc[i][2] + bb2)));
        }
    }
}

// ---------------- compositing: one warp per ray ----------------
__global__ void __launch_bounds__(256)
composite_kernel(float* __restrict__ out)
{
    const int gwarp = (blockIdx.x * blockDim.x + threadIdx.x) >> 5;
    const int lane = threadIdx.x & 31;
    if (gwarp >= N_RAYS) return;
    const int r = gwarp;

    float T = 1.0f, wsum = 0.0f, a0 = 0.0f, a1 = 0.0f, a2 = 0.0f;
#pragma unroll
    for (int chunk = 0; chunk < N_SAMPLES / 32; chunk++) {
        const int off = r * N_SAMPLES + chunk * 32 + lane;
        const float alpha = g_alpha[off];
        const float c0 = g_rgb0[off];
        const float c1 = g_rgb1[off];
        const float c2 = g_rgb2[off];
        float p = 1.0f - alpha + 1e-10f;
#pragma unroll
        for (int d = 1; d < 32; d <<= 1) {
            const float up = __shfl_up_sync(0xFFFFFFFFu, p, d);
            if (lane >= d) p *= up;
        }
        float excl = __shfl_up_sync(0xFFFFFFFFu, p, 1);
        if (lane == 0) excl = 1.0f;
        const float w = alpha * T * excl;
        wsum += w;
        a0 += w * c0; a1 += w * c1; a2 += w * c2;
        T *= __shfl_sync(0xFFFFFFFFu, p, 31);
    }
#pragma unroll
    for (int d = 16; d > 0; d >>= 1) {
        wsum += __shfl_down_sync(0xFFFFFFFFu, wsum, d);
        a0 += __shfl_down_sync(0xFFFFFFFFu, a0, d);
        a1 += __shfl_down_sync(0xFFFFFFFFu, a1, d);
        a2 += __shfl_down_sync(0xFFFFFFFFu, a2, d);
    }
    if (lane == 0) {
        const float bg = 1.0f - wsum;
        out[r * 3 + 0] = a0 + bg;
        out[r * 3 + 1] = a1 + bg;
        out[r * 3 + 2] = a2 + bg;
    }
}

extern "C" void kernel_launch(void* const* d_in, const int* in_sizes, int n_in,
                              void* d_out, int out_size)
{
    const float* rays_o = (const float*)d_in[0];
    const float* rays_d = (const float*)d_in[1];
    const float* dgrid  = (const float*)d_in[2];
    const float* k0grid = (const float*)d_in[3];
    const float* w0 = (const float*)d_in[4];
    const float* b0 = (const float*)d_in[5];
    const float* w1 = (const float*)d_in[6];
    const float* b1 = (const float*)d_in[7];
    const float* w2 = (const float*)d_in[8];
    const float* b2 = (const float*)d_in[9];
    float* out = (float*)d_out;

    cudaFuncSetAttribute(point_kernel,
                         cudaFuncAttributeMaxDynamicSharedMemorySize, SMEM_BYTES);

    prep_kernel<<<48, 256>>>(w0, w1);
    point_kernel<<<NPTS / 128, 128, SMEM_BYTES>>>(rays_o, rays_d, dgrid, k0grid,
                                                  w2, b0, b1, b2);
    composite_kernel<<<(N_RAYS * 32 + 255) / 256, 256>>>(out);
}

// round 9
// speedup vs baseline: 6.8028x; 1.9197x over previous
#include <cuda_runtime.h>
#include <cstdint>
#include <math.h>

#define N_RAYS 4096
#define N_SAMPLES 192
#define GRID_D 160
#define GRID_D2 (160*160)
#define GRID_D3 (160*160*160)
#define K0_DIM 12
#define XYZ_MIN (-1.2f)
#define COORD_SCALE (159.0f / 2.4f)
#define ACT_SHIFT (-4.595119850134589f)
#define STEPDIST (2.8f / 192.0f)
#define NEARV 0.2f
#define FARV 3.0f

#define NPTS (N_RAYS * N_SAMPLES)

// ---------------- scratch ----------------
__device__ float g_alpha[NPTS];
__device__ float g_rgb0[NPTS];
__device__ float g_rgb1[NPTS];
__device__ float g_rgb2[NPTS];
// prepacked transposed bf16x2 weights, padded strides for conflict-free LDS
__device__ uint32_t PW0T[128 * 28];   // [n][kpair], k<39 real (pad to 48)
__device__ uint32_t PW1T[128 * 68];   // [n][kpair], k<128 real
// AoS packed grid: per voxel 16 bf16 (32B) = [density, k0_0..k0_11, pad,pad,pad]
__device__ uint4 PG[GRID_D3 * 2];     // 131 MB

// ---------------- smem layout (4-byte word units) ----------------
#define SM_W0T 0                       /* 128*28 = 3584 */
#define SM_W1T 3584                    /* 128*68 = 8704 */
#define SM_F   (SM_W1T + 8704)         /* 128*28 = 3584 */
#define SM_W2  (SM_F + 3584)           /* 384 */
#define SM_B0  (SM_W2 + 384)
#define SM_B1  (SM_B0 + 128)
#define SM_B2  (SM_B1 + 128)
#define SM_WORDS (SM_B2 + 4)
#define SMEM_BYTES (SM_WORDS * 4)      /* ~64.5 KB -> 3 CTAs/SM */

__device__ __forceinline__ uint32_t pack_bf16x2(float lo, float hi) {
    uint32_t u;
    asm("cvt.rn.bf16x2.f32 %0, %1, %2;" : "=r"(u) : "f"(hi), "f"(lo));
    return u;
}
__device__ __forceinline__ float bflo(uint32_t u) { return __uint_as_float(u << 16); }
__device__ __forceinline__ float bfhi(uint32_t u) { return __uint_as_float(u & 0xffff0000u); }

__device__ __forceinline__ void mma_bf16(float c[4],
                                         uint32_t a0, uint32_t a1, uint32_t a2, uint32_t a3,
                                         uint32_t b0, uint32_t b1) {
    asm volatile("mma.sync.aligned.m16n8k16.row.col.f32.bf16.bf16.f32 "
                 "{%0,%1,%2,%3}, {%4,%5,%6,%7}, {%8,%9}, {%0,%1,%2,%3};"
                 : "+f"(c[0]), "+f"(c[1]), "+f"(c[2]), "+f"(c[3])
                 : "r"(a0), "r"(a1), "r"(a2), "r"(a3), "r"(b0), "r"(b1));
}

// ---------------- prep: pack W0^T / W1^T bf16x2, padded ----------------
__global__ void prep_kernel(const float* __restrict__ w0, const float* __restrict__ w1)
{
    const int t = blockIdx.x * blockDim.x + threadIdx.x;
    const int stride = gridDim.x * blockDim.x;
    for (int i = t; i < 128 * 28; i += stride) {
        const int n = i / 28, wd = i - n * 28;
        const int k = 2 * wd;
        const float lo = (k < 39) ? w0[k * 128 + n] : 0.0f;
        const float hi = (k + 1 < 39) ? w0[(k + 1) * 128 + n] : 0.0f;
        PW0T[i] = pack_bf16x2(lo, hi);
    }
    for (int i = t; i < 128 * 68; i += stride) {
        const int n = i / 68, wd = i - n * 68;
        const int k = 2 * wd;
        const float lo = (k < 128) ? w1[k * 128 + n] : 0.0f;
        const float hi = (k + 1 < 128) ? w1[(k + 1) * 128 + n] : 0.0f;
        PW1T[i] = pack_bf16x2(lo, hi);
    }
}

// ---------------- pack grids into AoS bf16 voxels ----------------
__global__ void __launch_bounds__(256)
pack_grid_kernel(const float* __restrict__ dgrid, const float* __restrict__ k0grid)
{
    const int v = blockIdx.x * blockDim.x + threadIdx.x;
    if (v >= GRID_D3) return;
    float vals[14];
    vals[0] = dgrid[v];
#pragma unroll
    for (int c = 0; c < K0_DIM; c++) vals[1 + c] = k0grid[c * GRID_D3 + v];
    vals[13] = 0.0f;
    uint32_t w[8];
#pragma unroll
    for (int j = 0; j < 7; j++) w[j] = pack_bf16x2(vals[2 * j], vals[2 * j + 1]);
    w[7] = 0u;
    PG[v * 2 + 0] = make_uint4(w[0], w[1], w[2], w[3]);
    PG[v * 2 + 1] = make_uint4(w[4], w[5], w[6], w[7]);
}

// ---------------- point kernel: 128 samples / block, 3 CTAs/SM ----------------
__global__ void __launch_bounds__(128, 3)
point_kernel(const float* __restrict__ rays_o,
             const float* __restrict__ rays_d,
             const float* __restrict__ w2,
             const float* __restrict__ b0,
             const float* __restrict__ b1,
             const float* __restrict__ b2)
{
    extern __shared__ float sm[];
    uint32_t* smw = (uint32_t*)sm;
    const int tid = threadIdx.x;

    // ---- stage prepacked weights (coalesced; completes at syncthreads) ----
    {
        float4* d0 = (float4*)(smw + SM_W0T);
        const float4* s0 = (const float4*)PW0T;
        for (int i = tid; i < 896; i += 128) d0[i] = s0[i];
        float4* d1 = (float4*)(smw + SM_W1T);
        const float4* s1 = (const float4*)PW1T;
        for (int i = tid; i < 2176; i += 128) d1[i] = s1[i];
    }
    for (int i = tid; i < 384; i += 128) sm[SM_W2 + i] = w2[i];
    sm[SM_B0 + tid] = b0[tid];
    sm[SM_B1 + tid] = b1[tid];
    if (tid < 3) sm[SM_B2 + tid] = b2[tid];

    // ---- per-sample point ----
    const int idx = blockIdx.x * 128 + tid;
    const int r = idx / N_SAMPLES;
    const int s = idx - r * N_SAMPLES;

    float dx = rays_d[r * 3 + 0], dy = rays_d[r * 3 + 1], dz = rays_d[r * 3 + 2];
    const float inv = rsqrtf(dx * dx + dy * dy + dz * dz);
    const float vx = dx * inv, vy = dy * inv, vz = dz * inv;
    const float tval = NEARV + (FARV - NEARV) * ((float)s + 0.5f) / (float)N_SAMPLES;
    float px = rays_o[r * 3 + 0] + vx * tval;
    float py = rays_o[r * 3 + 1] + vy * tval;
    float pz = rays_o[r * 3 + 2] + vz * tval;
    const float nrm = fmaxf(fabsf(px), fmaxf(fabsf(py), fabsf(pz)));
    if (nrm > 1.0f) {
        const float invn = 1.0f / nrm;
        const float sc = (1.2f - 0.2f * invn) * invn;
        px *= sc; py *= sc; pz *= sc;
    }
    float gx = (px - XYZ_MIN) * COORD_SCALE;
    float gy = (py - XYZ_MIN) * COORD_SCALE;
    float gz = (pz - XYZ_MIN) * COORD_SCALE;
    gx = fminf(fmaxf(gx, 0.0f), 159.0f);
    gy = fminf(fmaxf(gy, 0.0f), 159.0f);
    gz = fminf(fmaxf(gz, 0.0f), 159.0f);
    const int ix = min((int)floorf(gx), 158);
    const int iy = min((int)floorf(gy), 158);
    const int iz = min((int)floorf(gz), 158);
    const float fx = gx - (float)ix, fy = gy - (float)iy, fz = gz - (float)iz;
    const float ex = 1.0f - fx, ey = 1.0f - fy, ez = 1.0f - fz;
    const int base = ix * GRID_D2 + iy * GRID_D + iz;

    // ---- AoS gather: 4 corner-pairs, 64B contiguous each (z & z+1) ----
    float acc13[13];
#pragma unroll
    for (int c = 0; c < 13; c++) acc13[c] = 0.0f;
    {
        const float wxy[4] = {ex * ey, ex * fy, fx * ey, fx * fy};
        const int vb[4] = {base, base + GRID_D, base + GRID_D2, base + GRID_D2 + GRID_D};
#pragma unroll
        for (int p = 0; p < 4; p++) {
            const uint4* src = PG + (size_t)vb[p] * 2;
            const uint4 q0 = src[0];
            const uint4 q1 = src[1];
            const uint4 q2 = src[2];
            const uint4 q3 = src[3];
            const float wz0 = wxy[p] * ez, wz1 = wxy[p] * fz;
            const uint32_t z0w[7] = {q0.x, q0.y, q0.z, q0.w, q1.x, q1.y, q1.z};
            const uint32_t z1w[7] = {q2.x, q2.y, q2.z, q2.w, q3.x, q3.y, q3.z};
#pragma unroll
            for (int j = 0; j < 7; j++) {
                const int c0 = 2 * j;
                acc13[c0] += bflo(z0w[j]) * wz0 + bflo(z1w[j]) * wz1;
                if (c0 + 1 < 13)
                    acc13[c0 + 1] += bfhi(z0w[j]) * wz0 + bfhi(z1w[j]) * wz1;
            }
        }
    }

    // ---- density -> alpha ----
    {
        const float x = acc13[0] + ACT_SHIFT;
        const float sigma = fmaxf(x, 0.0f) + log1pf(__expf(-fabsf(x)));
        g_alpha[idx] = 1.0f - __expf(-sigma * STEPDIST);
    }

    // ---- features ----
    float feat[48];
#pragma unroll
    for (int c = 0; c < K0_DIM; c++) feat[c] = acc13[c + 1];
    feat[12] = vx; feat[13] = vy; feat[14] = vz;
    {
        const float v3[3] = {vx, vy, vz};
#pragma unroll
        for (int i = 0; i < 3; i++) {
#pragma unroll
            for (int p = 0; p < 4; p++) {
                float sv, cv;
                __sincosf(v3[i] * (float)(1 << p), &sv, &cv);
                feat[15 + i * 4 + p] = sv;
                feat[27 + i * 4 + p] = cv;
            }
        }
    }
#pragma unroll
    for (int j = 39; j < 48; j++) feat[j] = 0.0f;

    // feature row -> smem bf16x2, row = tid, stride 28 words (56 bf16)
    {
        uint32_t* F = smw + SM_F;
#pragma unroll
        for (int j = 0; j < 24; j++)
            F[tid * 28 + j] = pack_bf16x2(feat[2 * j], feat[2 * j + 1]);
    }

    __syncthreads();   // weights staged

    const int lane = tid & 31;
    const int warp = tid >> 5;
    const int g8 = lane >> 2;      // groupID 0..7
    const int q = lane & 3;        // threadID_in_group
    const int m0 = warp * 32;

    const uint32_t* F   = smw + SM_F;
    const uint32_t* W0T = smw + SM_W0T;
    const uint32_t* W1T = smw + SM_W1T;

    // ---- layer 0: [128x48] @ [48x128] bf16 (3 k-steps) ----
    uint32_t af[2][3][4];
#pragma unroll
    for (int t = 0; t < 2; t++) {
        const int r0 = m0 + 16 * t;
#pragma unroll
        for (int kk = 0; kk < 3; kk++) {
            const int w = kk * 8 + q;
            af[t][kk][0] = F[(r0 + g8) * 28 + w];
            af[t][kk][1] = F[(r0 + 8 + g8) * 28 + w];
            af[t][kk][2] = F[(r0 + g8) * 28 + w + 4];
            af[t][kk][3] = F[(r0 + 8 + g8) * 28 + w + 4];
        }
    }

    // layer-0 C fragments convert DIRECTLY to layer-1 A fragments in registers.
    uint32_t a1f[2][8][4];
#pragma unroll
    for (int nt = 0; nt < 16; nt++) {
        const int n0 = nt * 8;
        const float cb0 = sm[SM_B0 + n0 + 2 * q];
        const float cb1 = sm[SM_B0 + n0 + 2 * q + 1];
        float C0[4] = {cb0, cb1, cb0, cb1};
        float C1[4] = {cb0, cb1, cb0, cb1};
#pragma unroll
        for (int kk = 0; kk < 3; kk++) {
            const int w = kk * 8 + q;
            const uint32_t bb0 = W0T[(n0 + g8) * 28 + w];
            const uint32_t bb1 = W0T[(n0 + g8) * 28 + w + 4];
            mma_bf16(C0, af[0][kk][0], af[0][kk][1], af[0][kk][2], af[0][kk][3], bb0, bb1);
            mma_bf16(C1, af[1][kk][0], af[1][kk][1], af[1][kk][2], af[1][kk][3], bb0, bb1);
        }
        const int kk1 = nt >> 1;
        const int hi = (nt & 1) << 1;
        a1f[0][kk1][hi]     = pack_bf16x2(fmaxf(C0[0], 0.0f), fmaxf(C0[1], 0.0f));
        a1f[0][kk1][hi + 1] = pack_bf16x2(fmaxf(C0[2], 0.0f), fmaxf(C0[3], 0.0f));
        a1f[1][kk1][hi]     = pack_bf16x2(fmaxf(C1[0], 0.0f), fmaxf(C1[1], 0.0f));
        a1f[1][kk1][hi + 1] = pack_bf16x2(fmaxf(C1[2], 0.0f), fmaxf(C1[3], 0.0f));
    }

    // ---- layer 1 + fused layer 2 ----
    float acc[4][3];
#pragma unroll
    for (int i = 0; i < 4; i++)
#pragma unroll
        for (int c = 0; c < 3; c++) acc[i][c] = 0.0f;

    const float* W2s = sm + SM_W2;
#pragma unroll
    for (int nt = 0; nt < 16; nt++) {
        const int n0 = nt * 8;
        const float cb0 = sm[SM_B1 + n0 + 2 * q];
        const float cb1 = sm[SM_B1 + n0 + 2 * q + 1];
        float C0[4] = {cb0, cb1, cb0, cb1};
        float C1[4] = {cb0, cb1, cb0, cb1};
#pragma unroll
        for (int kk = 0; kk < 8; kk++) {
            const int w = kk * 8 + q;
            const uint32_t bb0 = W1T[(n0 + g8) * 68 + w];
            const uint32_t bb1 = W1T[(n0 + g8) * 68 + w + 4];
            mma_bf16(C0, a1f[0][kk][0], a1f[0][kk][1], a1f[0][kk][2], a1f[0][kk][3], bb0, bb1);
            mma_bf16(C1, a1f[1][kk][0], a1f[1][kk][1], a1f[1][kk][2], a1f[1][kk][3], bb0, bb1);
        }
        const int col0 = n0 + 2 * q, col1 = col0 + 1;
        const float w20x = W2s[col0 * 3 + 0], w20y = W2s[col0 * 3 + 1], w20z = W2s[col0 * 3 + 2];
        const float w21x = W2s[col1 * 3 + 0], w21y = W2s[col1 * 3 + 1], w21z = W2s[col1 * 3 + 2];
        {
            const float h0 = fmaxf(C0[0], 0.0f), h1 = fmaxf(C0[1], 0.0f);
            const float h2 = fmaxf(C0[2], 0.0f), h3 = fmaxf(C0[3], 0.0f);
            acc[0][0] += h0 * w20x + h1 * w21x;
            acc[0][1] += h0 * w20y + h1 * w21y;
            acc[0][2] += h0 * w20z + h1 * w21z;
            acc[1][0] += h2 * w20x + h3 * w21x;
            acc[1][1] += h2 * w20y + h3 * w21y;
            acc[1][2] += h2 * w20z + h3 * w21z;
        }
        {
            const float h0 = fmaxf(C1[0], 0.0f), h1 = fmaxf(C1[1], 0.0f);
            const float h2 = fmaxf(C1[2], 0.0f), h3 = fmaxf(C1[3], 0.0f);
            acc[2][0] += h0 * w20x + h1 * w21x;
            acc[2][1] += h0 * w20y + h1 * w21y;
            acc[2][2] += h0 * w20z + h1 * w21z;
            acc[3][0] += h2 * w20x + h3 * w21x;
            acc[3][1] += h2 * w20y + h3 * w21y;
            acc[3][2] += h2 * w20z + h3 * w21z;
        }
    }

    // quad reduction
#pragma unroll
    for (int i = 0; i < 4; i++)
#pragma unroll
        for (int c = 0; c < 3; c++) {
            acc[i][c] += __shfl_xor_sync(0xFFFFFFFFu, acc[i][c], 1);
            acc[i][c] += __shfl_xor_sync(0xFFFFFFFFu, acc[i][c], 2);
        }

    if (q == 0) {
        const float bb0 = sm[SM_B2 + 0], bb1 = sm[SM_B2 + 1], bb2 = sm[SM_B2 + 2];
        const int rows[4] = {m0 + g8, m0 + 8 + g8, m0 + 16 + g8, m0 + 24 + g8};
#pragma unroll
        for (int i = 0; i < 4; i++) {
            const int oidx = blockIdx.x * 128 + rows[i];
            g_rgb0[oidx] = 1.0f / (1.0f + __expf(-(acc[i][0] + bb0)));
            g_rgb1[oidx] = 1.0f / (1.0f + __expf(-(acc[i][1] + bb1)));
            g_rgb2[oidx] = 1.0f / (1.0f + __expf(-(acc[i][2] + bb2)));
        }
    }
}

// ---------------- compositing: one warp per ray ----------------
__global__ void __launch_bounds__(256)
composite_kernel(float* __restrict__ out)
{
    const int gwarp = (blockIdx.x * blockDim.x + threadIdx.x) >> 5;
    const int lane = threadIdx.x & 31;
    if (gwarp >= N_RAYS) return;
    const int r = gwarp;

    float T = 1.0f, wsum = 0.0f, a0 = 0.0f, a1 = 0.0f, a2 = 0.0f;
#pragma unroll
    for (int chunk = 0; chunk < N_SAMPLES / 32; chunk++) {
        const int off = r * N_SAMPLES + chunk * 32 + lane;
        const float alpha = g_alpha[off];
        const float c0 = g_rgb0[off];
        const float c1 = g_rgb1[off];
        const float c2 = g_rgb2[off];
        float p = 1.0f - alpha + 1e-10f;
#pragma unroll
        for (int d = 1; d < 32; d <<= 1) {
            const float up = __shfl_up_sync(0xFFFFFFFFu, p, d);
            if (lane >= d) p *= up;
        }
        float excl = __shfl_up_sync(0xFFFFFFFFu, p, 1);
        if (lane == 0) excl = 1.0f;
        const float w = alpha * T * excl;
        wsum += w;
        a0 += w * c0; a1 += w * c1; a2 += w * c2;
        T *= __shfl_sync(0xFFFFFFFFu, p, 31);
    }
#pragma unroll
    for (int d = 16; d > 0; d >>= 1) {
        wsum += __shfl_down_sync(0xFFFFFFFFu, wsum, d);
        a0 += __shfl_down_sync(0xFFFFFFFFu, a0, d);
        a1 += __shfl_down_sync(0xFFFFFFFFu, a1, d);
        a2 += __shfl_down_sync(0xFFFFFFFFu, a2, d);
    }
    if (lane == 0) {
        const float bg = 1.0f - wsum;
        out[r * 3 + 0] = a0 + bg;
        out[r * 3 + 1] = a1 + bg;
        out[r * 3 + 2] = a2 + bg;
    }
}

extern "C" void kernel_launch(void* const* d_in, const int* in_sizes, int n_in,
                              void* d_out, int out_size)
{
    const float* rays_o = (const float*)d_in[0];
    const float* rays_d = (const float*)d_in[1];
    const float* dgrid  = (const float*)d_in[2];
    const float* k0grid = (const float*)d_in[3];
    const float* w0 = (const float*)d_in[4];
    const float* b0 = (const float*)d_in[5];
    const float* w1 = (const float*)d_in[6];
    const float* b1 = (const float*)d_in[7];
    const float* w2 = (const float*)d_in[8];
    const float* b2 = (const float*)d_in[9];
    float* out = (float*)d_out;

    cudaFuncSetAttribute(point_kernel,
                         cudaFuncAttributeMaxDynamicSharedMemorySize, SMEM_BYTES);

    prep_kernel<<<48, 256>>>(w0, w1);
    pack_grid_kernel<<<(GRID_D3 + 255) / 256, 256>>>(dgrid, k0grid);
    point_kernel<<<NPTS / 128, 128, SMEM_BYTES>>>(rays_o, rays_d, w2, b0, b1, b2);
    composite_kernel<<<(N_RAYS * 32 + 255) / 256, 256>>>(out);
}

// round 11
// speedup vs baseline: 8.8721x; 1.3042x over previous
#include <cuda_runtime.h>
#include <cstdint>
#include <math.h>

#define N_RAYS 4096
#define N_SAMPLES 192
#define GRID_D 160
#define GRID_D2 (160*160)
#define GRID_D3 (160*160*160)
#define K0_DIM 12
#define XYZ_MIN (-1.2f)
#define COORD_SCALE (159.0f / 2.4f)
#define ACT_SHIFT (-4.595119850134589f)
#define STEPDIST (2.8f / 192.0f)
#define NEARV 0.2f
#define FARV 3.0f

#define NPTS (N_RAYS * N_SAMPLES)
#define BLOCK 256

// ---------------- scratch ----------------
__device__ float g_alpha[NPTS];
__device__ float g_rgb0[NPTS];
__device__ float g_rgb1[NPTS];
__device__ float g_rgb2[NPTS];
// prepacked transposed bf16x2 weights, padded strides for conflict-free LDS
__device__ uint32_t PW0T[128 * 28];   // [n][kpair], k<39 real (pad to 48)
__device__ uint32_t PW1T[128 * 68];   // [n][kpair], k<128 real
// AoS packed grid: per voxel 16 bf16 (32B) = [density, k0_0..k0_11, pad,pad,pad]
__device__ uint4 PG[GRID_D3 * 2];     // 131 MB

// ---------------- smem layout (4-byte word units) ----------------
#define SM_W0T 0                       /* 128*28 = 3584 */
#define SM_W1T 3584                    /* 128*68 = 8704 */
#define SM_F   12288                   /* 256*28 = 7168 */
#define SM_W2  19456                   /* 384 */
#define SM_B0  19840
#define SM_B1  19968
#define SM_B2  20096
#define SM_WORDS 20100
#define SMEM_BYTES (SM_WORDS * 4)      /* ~78.5 KB -> 2 CTAs/SM (512 thr) */

__device__ __forceinline__ uint32_t pack_bf16x2(float lo, float hi) {
    uint32_t u;
    asm("cvt.rn.bf16x2.f32 %0, %1, %2;" : "=r"(u) : "f"(hi), "f"(lo));
    return u;
}
__device__ __forceinline__ float bflo(uint32_t u) { return __uint_as_float(u << 16); }
__device__ __forceinline__ float bfhi(uint32_t u) { return __uint_as_float(u & 0xffff0000u); }

__device__ __forceinline__ uint32_t smem_u32(const void* p) {
    uint32_t a;
    asm("{ .reg .u64 t; cvta.to.shared.u64 t, %1; cvt.u32.u64 %0, t; }" : "=r"(a) : "l"(p));
    return a;
}
__device__ __forceinline__ void ldsm_x4(uint32_t& r0, uint32_t& r1, uint32_t& r2, uint32_t& r3,
                                        uint32_t addr) {
    asm volatile("ldmatrix.sync.aligned.m8n8.x4.shared.b16 {%0,%1,%2,%3}, [%4];"
                 : "=r"(r0), "=r"(r1), "=r"(r2), "=r"(r3) : "r"(addr));
}
__device__ __forceinline__ void ldsm_x2(uint32_t& r0, uint32_t& r1, uint32_t addr) {
    asm volatile("ldmatrix.sync.aligned.m8n8.x2.shared.b16 {%0,%1}, [%2];"
                 : "=r"(r0), "=r"(r1) : "r"(addr));
}

__device__ __forceinline__ void mma_bf16(float c[4],
                                         uint32_t a0, uint32_t a1, uint32_t a2, uint32_t a3,
                                         uint32_t b0, uint32_t b1) {
    asm volatile("mma.sync.aligned.m16n8k16.row.col.f32.bf16.bf16.f32 "
                 "{%0,%1,%2,%3}, {%4,%5,%6,%7}, {%8,%9}, {%0,%1,%2,%3};"
                 : "+f"(c[0]), "+f"(c[1]), "+f"(c[2]), "+f"(c[3])
                 : "r"(a0), "r"(a1), "r"(a2), "r"(a3), "r"(b0), "r"(b1));
}

// ---------------- prep: pack W0^T / W1^T bf16x2, padded ----------------
__global__ void prep_kernel(const float* __restrict__ w0, const float* __restrict__ w1)
{
    const int t = blockIdx.x * blockDim.x + threadIdx.x;
    const int stride = gridDim.x * blockDim.x;
    for (int i = t; i < 128 * 28; i += stride) {
        const int n = i / 28, wd = i - n * 28;
        const int k = 2 * wd;
        const float lo = (k < 39) ? w0[k * 128 + n] : 0.0f;
        const float hi = (k + 1 < 39) ? w0[(k + 1) * 128 + n] : 0.0f;
        PW0T[i] = pack_bf16x2(lo, hi);
    }
    for (int i = t; i < 128 * 68; i += stride) {
        const int n = i / 68, wd = i - n * 68;
        const int k = 2 * wd;
        const float lo = (k < 128) ? w1[k * 128 + n] : 0.0f;
        const float hi = (k + 1 < 128) ? w1[(k + 1) * 128 + n] : 0.0f;
        PW1T[i] = pack_bf16x2(lo, hi);
    }
}

// ---------------- pack grids into AoS bf16 voxels ----------------
__global__ void __launch_bounds__(256)
pack_grid_kernel(const float* __restrict__ dgrid, const float* __restrict__ k0grid)
{
    const int v = blockIdx.x * blockDim.x + threadIdx.x;
    if (v >= GRID_D3) return;
    float vals[14];
    vals[0] = dgrid[v];
#pragma unroll
    for (int c = 0; c < K0_DIM; c++) vals[1 + c] = k0grid[c * GRID_D3 + v];
    vals[13] = 0.0f;
    uint32_t w[8];
#pragma unroll
    for (int j = 0; j < 7; j++) w[j] = pack_bf16x2(vals[2 * j], vals[2 * j + 1]);
    w[7] = 0u;
    PG[v * 2 + 0] = make_uint4(w[0], w[1], w[2], w[3]);
    PG[v * 2 + 1] = make_uint4(w[4], w[5], w[6], w[7]);
}

// ---------------- point kernel: 256 samples / block, 2 CTAs/SM ----------------
__global__ void __launch_bounds__(BLOCK, 2)
point_kernel(const float* __restrict__ rays_o,
             const float* __restrict__ rays_d,
             const float* __restrict__ w2,
             const float* __restrict__ b0,
             const float* __restrict__ b1,
             const float* __restrict__ b2)
{
    extern __shared__ float sm[];
    uint32_t* smw = (uint32_t*)sm;
    const int tid = threadIdx.x;

    // ---- stage prepacked weights (coalesced; completes at syncthreads) ----
    {
        float4* d0 = (float4*)(smw + SM_W0T);
        const float4* s0 = (const float4*)PW0T;
        for (int i = tid; i < 896; i += BLOCK) d0[i] = s0[i];
        float4* d1 = (float4*)(smw + SM_W1T);
        const float4* s1 = (const float4*)PW1T;
        for (int i = tid; i < 2176; i += BLOCK) d1[i] = s1[i];
    }
    for (int i = tid; i < 384; i += BLOCK) sm[SM_W2 + i] = w2[i];
    if (tid < 128) {
        sm[SM_B0 + tid] = b0[tid];
        sm[SM_B1 + tid] = b1[tid];
    }
    if (tid < 3) sm[SM_B2 + tid] = b2[tid];

    // ---- per-sample point ----
    const int idx = blockIdx.x * BLOCK + tid;
    const int r = idx / N_SAMPLES;
    const int s = idx - r * N_SAMPLES;

    float dx = rays_d[r * 3 + 0], dy = rays_d[r * 3 + 1], dz = rays_d[r * 3 + 2];
    const float inv = rsqrtf(dx * dx + dy * dy + dz * dz);
    const float vx = dx * inv, vy = dy * inv, vz = dz * inv;
    const float tval = NEARV + (FARV - NEARV) * ((float)s + 0.5f) / (float)N_SAMPLES;
    float px = rays_o[r * 3 + 0] + vx * tval;
    float py = rays_o[r * 3 + 1] + vy * tval;
    float pz = rays_o[r * 3 + 2] + vz * tval;
    const float nrm = fmaxf(fabsf(px), fmaxf(fabsf(py), fabsf(pz)));
    if (nrm > 1.0f) {
        const float invn = 1.0f / nrm;
        const float sc = (1.2f - 0.2f * invn) * invn;
        px *= sc; py *= sc; pz *= sc;
    }
    float gx = (px - XYZ_MIN) * COORD_SCALE;
    float gy = (py - XYZ_MIN) * COORD_SCALE;
    float gz = (pz - XYZ_MIN) * COORD_SCALE;
    gx = fminf(fmaxf(gx, 0.0f), 159.0f);
    gy = fminf(fmaxf(gy, 0.0f), 159.0f);
    gz = fminf(fmaxf(gz, 0.0f), 159.0f);
    const int ix = min((int)floorf(gx), 158);
    const int iy = min((int)floorf(gy), 158);
    const int iz = min((int)floorf(gz), 158);
    const float fx = gx - (float)ix, fy = gy - (float)iy, fz = gz - (float)iz;
    const float ex = 1.0f - fx, ey = 1.0f - fy, ez = 1.0f - fz;
    const int base = ix * GRID_D2 + iy * GRID_D + iz;

    // ---- AoS gather: 4 corner-pairs, 64B contiguous each (z & z+1) ----
    float acc13[13];
#pragma unroll
    for (int c = 0; c < 13; c++) acc13[c] = 0.0f;
    {
        const float wxy[4] = {ex * ey, ex * fy, fx * ey, fx * fy};
        const int vb[4] = {base, base + GRID_D, base + GRID_D2, base + GRID_D2 + GRID_D};
#pragma unroll
        for (int p = 0; p < 4; p++) {
            const uint4* src = PG + (size_t)vb[p] * 2;
            const uint4 q0 = src[0];
            const uint4 q1 = src[1];
            const uint4 q2 = src[2];
            const uint4 q3 = src[3];
            const float wz0 = wxy[p] * ez, wz1 = wxy[p] * fz;
            const uint32_t z0w[7] = {q0.x, q0.y, q0.z, q0.w, q1.x, q1.y, q1.z};
            const uint32_t z1w[7] = {q2.x, q2.y, q2.z, q2.w, q3.x, q3.y, q3.z};
#pragma unroll
            for (int j = 0; j < 7; j++) {
                const int c0 = 2 * j;
                acc13[c0] += bflo(z0w[j]) * wz0 + bflo(z1w[j]) * wz1;
                if (c0 + 1 < 13)
                    acc13[c0 + 1] += bfhi(z0w[j]) * wz0 + bfhi(z1w[j]) * wz1;
            }
        }
    }

    // ---- density -> alpha ----
    {
        const float x = acc13[0] + ACT_SHIFT;
        const float sigma = fmaxf(x, 0.0f) + log1pf(__expf(-fabsf(x)));
        g_alpha[idx] = 1.0f - __expf(-sigma * STEPDIST);
    }

    // ---- features -> smem bf16x2, row = tid, stride 28 words ----
    {
        float feat[40];
#pragma unroll
        for (int c = 0; c < K0_DIM; c++) feat[c] = acc13[c + 1];
        feat[12] = vx; feat[13] = vy; feat[14] = vz;
        {
            const float v3[3] = {vx, vy, vz};
#pragma unroll
            for (int i = 0; i < 3; i++) {
#pragma unroll
                for (int p = 0; p < 4; p++) {
                    float sv, cv;
                    __sincosf(v3[i] * (float)(1 << p), &sv, &cv);
                    feat[15 + i * 4 + p] = sv;
                    feat[27 + i * 4 + p] = cv;
                }
            }
        }
        feat[39] = 0.0f;
        uint32_t* F = smw + SM_F;
#pragma unroll
        for (int j = 0; j < 20; j++)
            F[tid * 28 + j] = pack_bf16x2(feat[2 * j], feat[2 * j + 1]);
#pragma unroll
        for (int j = 20; j < 24; j++) F[tid * 28 + j] = 0u;
    }

    __syncthreads();   // weights + features staged

    const int lane = tid & 31;
    const int warp = tid >> 5;
    const int g8 = lane >> 2;      // groupID 0..7
    const int q = lane & 3;        // threadID_in_group
    const int m0 = warp * 32;
    const int arow = lane & 7;     // ldmatrix row provider
    const int amt = lane >> 3;     // ldmatrix matrix selector

    const uint32_t sm_base = smem_u32(sm);
    const uint32_t Fb  = sm_base + SM_F * 4;
    const uint32_t W0b = sm_base + SM_W0T * 4;
    const uint32_t W1b = sm_base + SM_W1T * 4;

    // ---- A fragments for layer 0 via ldmatrix.x4 (6 instrs) ----
    uint32_t af[2][3][4];
#pragma unroll
    for (int t = 0; t < 2; t++) {
#pragma unroll
        for (int kk = 0; kk < 3; kk++) {
            const uint32_t addr = Fb +
                (((m0 + 16 * t + ((amt & 1) << 3) + arow) * 28 + 8 * kk + ((amt >> 1) << 2)) << 2);
            ldsm_x4(af[t][kk][0], af[t][kk][1], af[t][kk][2], af[t][kk][3], addr);
        }
    }

    // ---- layer 0: C fragments become layer-1 A fragments directly in registers ----
    uint32_t a1f[2][8][4];
#pragma unroll
    for (int nt = 0; nt < 16; nt++) {
        const int n0 = nt * 8;
        const float cb0 = sm[SM_B0 + n0 + 2 * q];
        const float cb1 = sm[SM_B0 + n0 + 2 * q + 1];
        float C0[4] = {cb0, cb1, cb0, cb1};
        float C1[4] = {cb0, cb1, cb0, cb1};
        uint32_t bb[6];
        ldsm_x4(bb[0], bb[1], bb[2], bb[3],
                W0b + (((n0 + arow) * 28 + (amt << 2)) << 2));
        ldsm_x2(bb[4], bb[5],
                W0b + (((n0 + arow) * 28 + 16 + ((amt & 1) << 2)) << 2));
#pragma unroll
        for (int kk = 0; kk < 3; kk++) {
            mma_bf16(C0, af[0][kk][0], af[0][kk][1], af[0][kk][2], af[0][kk][3],
                     bb[2 * kk], bb[2 * kk + 1]);
            mma_bf16(C1, af[1][kk][0], af[1][kk][1], af[1][kk][2], af[1][kk][3],
                     bb[2 * kk], bb[2 * kk + 1]);
        }
        const int kk1 = nt >> 1;
        const int hi = (nt & 1) << 1;
        a1f[0][kk1][hi]     = pack_bf16x2(fmaxf(C0[0], 0.0f), fmaxf(C0[1], 0.0f));
        a1f[0][kk1][hi + 1] = pack_bf16x2(fmaxf(C0[2], 0.0f), fmaxf(C0[3], 0.0f));
        a1f[1][kk1][hi]     = pack_bf16x2(fmaxf(C1[0], 0.0f), fmaxf(C1[1], 0.0f));
        a1f[1][kk1][hi + 1] = pack_bf16x2(fmaxf(C1[2], 0.0f), fmaxf(C1[3], 0.0f));
    }

    // ---- layer 1 + fused layer 2 ----
    float acc[4][3];
#pragma unroll
    for (int i = 0; i < 4; i++)
#pragma unroll
        for (int c = 0; c < 3; c++) acc[i][c] = 0.0f;

    const float* W2s = sm + SM_W2;
#pragma unroll
    for (int nt = 0; nt < 16; nt++) {
        const int n0 = nt * 8;
        const float cb0 = sm[SM_B1 + n0 + 2 * q];
        const float cb1 = sm[SM_B1 + n0 + 2 * q + 1];
        float C0[4] = {cb0, cb1, cb0, cb1};
        float C1[4] = {cb0, cb1, cb0, cb1};
#pragma unroll
        for (int kp = 0; kp < 4; kp++) {
            uint32_t w0r, w1r, w2r, w3r;
            ldsm_x4(w0r, w1r, w2r, w3r,
                    W1b + (((n0 + arow) * 68 + 16 * kp + (amt << 2)) << 2));
            const int kk = 2 * kp;
            mma_bf16(C0, a1f[0][kk][0], a1f[0][kk][1], a1f[0][kk][2], a1f[0][kk][3], w0r, w1r);
            mma_bf16(C1, a1f[1][kk][0], a1f[1][kk][1], a1f[1][kk][2], a1f[1][kk][3], w0r, w1r);
            mma_bf16(C0, a1f[0][kk + 1][0], a1f[0][kk + 1][1], a1f[0][kk + 1][2], a1f[0][kk + 1][3], w2r, w3r);
            mma_bf16(C1, a1f[1][kk + 1][0], a1f[1][kk + 1][1], a1f[1][kk + 1][2], a1f[1][kk + 1][3], w2r, w3r);
        }
        const int col0 = n0 + 2 * q, col1 = col0 + 1;
        const float w20x = W2s[col0 * 3 + 0], w20y = W2s[col0 * 3 + 1], w20z = W2s[col0 * 3 + 2];
        const float w21x = W2s[col1 * 3 + 0], w21y = W2s[col1 * 3 + 1], w21z = W2s[col1 * 3 + 2];
        {
            const float h0 = fmaxf(C0[0], 0.0f), h1 = fmaxf(C0[1], 0.0f);
            const float h2 = fmaxf(C0[2], 0.0f), h3 = fmaxf(C0[3], 0.0f);
            acc[0][0] += h0 * w20x + h1 * w21x;
            acc[0][1] += h0 * w20y + h1 * w21y;
            acc[0][2] += h0 * w20z + h1 * w21z;
            acc[1][0] += h2 * w20x + h3 * w21x;
            acc[1][1] += h2 * w20y + h3 * w21y;
            acc[1][2] += h2 * w20z + h3 * w21z;
        }
        {
            const float h0 = fmaxf(C1[0], 0.0f), h1 = fmaxf(C1[1], 0.0f);
            const float h2 = fmaxf(C1[2], 0.0f), h3 = fmaxf(C1[3], 0.0f);
            acc[2][0] += h0 * w20x + h1 * w21x;
            acc[2][1] += h0 * w20y + h1 * w21y;
            acc[2][2] += h0 * w20z + h1 * w21z;
            acc[3][0] += h2 * w20x + h3 * w21x;
            acc[3][1] += h2 * w20y + h3 * w21y;
            acc[3][2] += h2 * w20z + h3 * w21z;
        }
    }

    // quad reduction
#pragma unroll
    for (int i = 0; i < 4; i++)
#pragma unroll
        for (int c = 0; c < 3; c++) {
            acc[i][c] += __shfl_xor_sync(0xFFFFFFFFu, acc[i][c], 1);
            acc[i][c] += __shfl_xor_sync(0xFFFFFFFFu, acc[i][c], 2);
        }

    if (q == 0) {
        const float bb0 = sm[SM_B2 + 0], bb1 = sm[SM_B2 + 1], bb2 = sm[SM_B2 + 2];
        const int rows[4] = {m0 + g8, m0 + 8 + g8, m0 + 16 + g8, m0 + 24 + g8};
#pragma unroll
        for (int i = 0; i < 4; i++) {
            const int oidx = blockIdx.x * BLOCK + rows[i];
            g_rgb0[oidx] = 1.0f / (1.0f + __expf(-(acc[i][0] + bb0)));
            g_rgb1[oidx] = 1.0f / (1.0f + __expf(-(acc[i][1] + bb1)));
            g_rgb2[oidx] = 1.0f / (1.0f + __expf(-(acc[i][2] + bb2)));
        }
    }
}

// ---------------- compositing: one warp per ray ----------------
__global__ void __launch_bounds__(256)
composite_kernel(float* __restrict__ out)
{
    const int gwarp = (blockIdx.x * blockDim.x + threadIdx.x) >> 5;
    const int lane = threadIdx.x & 31;
    if (gwarp >= N_RAYS) return;
    const int r = gwarp;

    float T = 1.0f, wsum = 0.0f, a0 = 0.0f, a1 = 0.0f, a2 = 0.0f;
#pragma unroll
    for (int chunk = 0; chunk < N_SAMPLES / 32; chunk++) {
        const int off = r * N_SAMPLES + chunk * 32 + lane;
        const float alpha = g_alpha[off];
        const float c0 = g_rgb0[off];
        const float c1 = g_rgb1[off];
        const float c2 = g_rgb2[off];
        float p = 1.0f - alpha + 1e-10f;
#pragma unroll
        for (int d = 1; d < 32; d <<= 1) {
            const float up = __shfl_up_sync(0xFFFFFFFFu, p, d);
            if (lane >= d) p *= up;
        }
        float excl = __shfl_up_sync(0xFFFFFFFFu, p, 1);
        if (lane == 0) excl = 1.0f;
        const float w = alpha * T * excl;
        wsum += w;
        a0 += w * c0; a1 += w * c1; a2 += w * c2;
        T *= __shfl_sync(0xFFFFFFFFu, p, 31);
    }
#pragma unroll
    for (int d = 16; d > 0; d >>= 1) {
        wsum += __shfl_down_sync(0xFFFFFFFFu, wsum, d);
        a0 += __shfl_down_sync(0xFFFFFFFFu, a0, d);
        a1 += __shfl_down_sync(0xFFFFFFFFu, a1, d);
        a2 += __shfl_down_sync(0xFFFFFFFFu, a2, d);
    }
    if (lane == 0) {
        const float bg = 1.0f - wsum;
        out[r * 3 + 0] = a0 + bg;
        out[r * 3 + 1] = a1 + bg;
        out[r * 3 + 2] = a2 + bg;
    }
}

extern "C" void kernel_launch(void* const* d_in, const int* in_sizes, int n_in,
                              void* d_out, int out_size)
{
    const float* rays_o = (const float*)d_in[0];
    const float* rays_d = (const float*)d_in[1];
    const float* dgrid  = (const float*)d_in[2];
    const float* k0grid = (const float*)d_in[3];
    const float* w0 = (const float*)d_in[4];
    const float* b0 = (const float*)d_in[5];
    const float* w1 = (const float*)d_in[6];
    const float* b1 = (const float*)d_in[7];
    const float* w2 = (const float*)d_in[8];
    const float* b2 = (const float*)d_in[9];
    float* out = (float*)d_out;

    cudaFuncSetAttribute(point_kernel,
                         cudaFuncAttributeMaxDynamicSharedMemorySize, SMEM_BYTES);

    prep_kernel<<<48, 256>>>(w0, w1);
    pack_grid_kernel<<<(GRID_D3 + 255) / 256, 256>>>(dgrid, k0grid);
    point_kernel<<<NPTS / BLOCK, BLOCK, SMEM_BYTES>>>(rays_o, rays_d, w2, b0, b1, b2);
    composite_kernel<<<(N_RAYS * 32 + 255) / 256, 256>>>(out);
}

// round 12
// speedup vs baseline: 9.7991x; 1.1045x over previous
#include <cuda_runtime.h>
#include <cuda_fp16.h>
#include <cstdint>
#include <math.h>

#define N_RAYS 4096
#define N_SAMPLES 192
#define GRID_D 160
#define GRID_D2 (160*160)
#define GRID_D3 (160*160*160)
#define K0_DIM 12
#define XYZ_MIN (-1.2f)
#define COORD_SCALE (159.0f / 2.4f)
#define ACT_SHIFT (-4.595119850134589f)
#define STEPDIST (2.8f / 192.0f)
#define NEARV 0.2f
#define FARV 3.0f

#define NPTS (N_RAYS * N_SAMPLES)
#define BLOCK 256

// ---------------- scratch ----------------
__device__ float g_alpha[NPTS];
__device__ float g_rgb0[NPTS];
__device__ float g_rgb1[NPTS];
__device__ float g_rgb2[NPTS];
// prepacked transposed bf16x2 weights, padded strides for conflict-free LDS
__device__ uint32_t PW0T[128 * 28];   // [n][kpair], k<39 real (pad to 48)
__device__ uint32_t PW1T[128 * 68];   // [n][kpair], k<128 real
// packed voxel: 16B = [density bf16 | k0[0..11] e4m3 | pad16]
__device__ uint4 PG[GRID_D3];         // 65.5 MB (L2-resident)

// ---------------- smem layout (4-byte word units) ----------------
#define SM_W0T 0                       /* 128*28 = 3584 */
#define SM_W1T 3584                    /* 128*68 = 8704 */
#define SM_F   12288                   /* 256*28 = 7168 */
#define SM_W2  19456                   /* 384 */
#define SM_B0  19840
#define SM_B1  19968
#define SM_B2  20096
#define SM_WORDS 20100
#define SMEM_BYTES (SM_WORDS * 4)      /* ~78.5 KB -> 2 CTAs/SM (512 thr) */

__device__ __forceinline__ uint32_t pack_bf16x2(float lo, float hi) {
    uint32_t u;
    asm("cvt.rn.bf16x2.f32 %0, %1, %2;" : "=r"(u) : "f"(hi), "f"(lo));
    return u;
}
__device__ __forceinline__ float bflo(uint32_t u) { return __uint_as_float(u << 16); }

__device__ __forceinline__ uint16_t pack_e4m3x2(float lo, float hi) {
    uint16_t r;
    asm("cvt.rn.satfinite.e4m3x2.f32 %0, %1, %2;" : "=h"(r) : "f"(hi), "f"(lo));
    return r;
}
__device__ __forceinline__ __half2 e4m3x2_to_h2(uint32_t u) {
    uint32_t h2;
    asm("cvt.rn.f16x2.e4m3x2 %0, %1;" : "=r"(h2) : "h"((uint16_t)(u)));
    return *reinterpret_cast<__half2*>(&h2);
}

__device__ __forceinline__ uint32_t smem_u32(const void* p) {
    uint32_t a;
    asm("{ .reg .u64 t; cvta.to.shared.u64 t, %1; cvt.u32.u64 %0, t; }" : "=r"(a) : "l"(p));
    return a;
}
__device__ __forceinline__ void ldsm_x4(uint32_t& r0, uint32_t& r1, uint32_t& r2, uint32_t& r3,
                                        uint32_t addr) {
    asm volatile("ldmatrix.sync.aligned.m8n8.x4.shared.b16 {%0,%1,%2,%3}, [%4];"
                 : "=r"(r0), "=r"(r1), "=r"(r2), "=r"(r3) : "r"(addr));
}
__device__ __forceinline__ void ldsm_x2(uint32_t& r0, uint32_t& r1, uint32_t addr) {
    asm volatile("ldmatrix.sync.aligned.m8n8.x2.shared.b16 {%0,%1}, [%2];"
                 : "=r"(r0), "=r"(r1) : "r"(addr));
}

__device__ __forceinline__ void mma_bf16(float c[4],
                                         uint32_t a0, uint32_t a1, uint32_t a2, uint32_t a3,
                                         uint32_t b0, uint32_t b1) {
    asm volatile("mma.sync.aligned.m16n8k16.row.col.f32.bf16.bf16.f32 "
                 "{%0,%1,%2,%3}, {%4,%5,%6,%7}, {%8,%9}, {%0,%1,%2,%3};"
                 : "+f"(c[0]), "+f"(c[1]), "+f"(c[2]), "+f"(c[3])
                 : "r"(a0), "r"(a1), "r"(a2), "r"(a3), "r"(b0), "r"(b1));
}

// ---------------- prep: pack W0^T / W1^T bf16x2, padded ----------------
__global__ void prep_kernel(const float* __restrict__ w0, const float* __restrict__ w1)
{
    const int t = blockIdx.x * blockDim.x + threadIdx.x;
    const int stride = gridDim.x * blockDim.x;
    for (int i = t; i < 128 * 28; i += stride) {
        const int n = i / 28, wd = i - n * 28;
        const int k = 2 * wd;
        const float lo = (k < 39) ? w0[k * 128 + n] : 0.0f;
        const float hi = (k + 1 < 39) ? w0[(k + 1) * 128 + n] : 0.0f;
        PW0T[i] = pack_bf16x2(lo, hi);
    }
    for (int i = t; i < 128 * 68; i += stride) {
        const int n = i / 68, wd = i - n * 68;
        const int k = 2 * wd;
        const float lo = (k < 128) ? w1[k * 128 + n] : 0.0f;
        const float hi = (k + 1 < 128) ? w1[(k + 1) * 128 + n] : 0.0f;
        PW1T[i] = pack_bf16x2(lo, hi);
    }
}

// ---------------- pack grids into 16B fp8/bf16 voxels ----------------
__global__ void __launch_bounds__(256)
pack_grid_kernel(const float* __restrict__ dgrid, const float* __restrict__ k0grid)
{
    const int v = blockIdx.x * blockDim.x + threadIdx.x;
    if (v >= GRID_D3) return;
    const float d = dgrid[v];
    float k[12];
#pragma unroll
    for (int c = 0; c < K0_DIM; c++) k[c] = k0grid[c * GRID_D3 + v];
    const uint32_t dbf = pack_bf16x2(d, 0.0f) & 0xffffu;
    const uint32_t w0 = dbf | ((uint32_t)pack_e4m3x2(k[0], k[1]) << 16);
    const uint32_t w1 = (uint32_t)pack_e4m3x2(k[2], k[3]) | ((uint32_t)pack_e4m3x2(k[4], k[5]) << 16);
    const uint32_t w2 = (uint32_t)pack_e4m3x2(k[6], k[7]) | ((uint32_t)pack_e4m3x2(k[8], k[9]) << 16);
    const uint32_t w3 = (uint32_t)pack_e4m3x2(k[10], k[11]);
    PG[v] = make_uint4(w0, w1, w2, w3);
}

// ---------------- point kernel: 256 samples / block, 2 CTAs/SM ----------------
__global__ void __launch_bounds__(BLOCK, 2)
point_kernel(const float* __restrict__ rays_o,
             const float* __restrict__ rays_d,
             const float* __restrict__ w2,
             const float* __restrict__ b0,
             const float* __restrict__ b1,
             const float* __restrict__ b2)
{
    extern __shared__ float sm[];
    uint32_t* smw = (uint32_t*)sm;
    const int tid = threadIdx.x;

    // ---- stage prepacked weights (coalesced; completes at syncthreads) ----
    {
        float4* d0 = (float4*)(smw + SM_W0T);
        const float4* s0 = (const float4*)PW0T;
        for (int i = tid; i < 896; i += BLOCK) d0[i] = s0[i];
        float4* d1 = (float4*)(smw + SM_W1T);
        const float4* s1 = (const float4*)PW1T;
        for (int i = tid; i < 2176; i += BLOCK) d1[i] = s1[i];
    }
    for (int i = tid; i < 384; i += BLOCK) sm[SM_W2 + i] = w2[i];
    if (tid < 128) {
        sm[SM_B0 + tid] = b0[tid];
        sm[SM_B1 + tid] = b1[tid];
    }
    if (tid < 3) sm[SM_B2 + tid] = b2[tid];

    // ---- per-sample point ----
    const int idx = blockIdx.x * BLOCK + tid;
    const int r = idx / N_SAMPLES;
    const int s = idx - r * N_SAMPLES;

    float dx = rays_d[r * 3 + 0], dy = rays_d[r * 3 + 1], dz = rays_d[r * 3 + 2];
    const float inv = rsqrtf(dx * dx + dy * dy + dz * dz);
    const float vx = dx * inv, vy = dy * inv, vz = dz * inv;
    const float tval = NEARV + (FARV - NEARV) * ((float)s + 0.5f) / (float)N_SAMPLES;
    float px = rays_o[r * 3 + 0] + vx * tval;
    float py = rays_o[r * 3 + 1] + vy * tval;
    float pz = rays_o[r * 3 + 2] + vz * tval;
    const float nrm = fmaxf(fabsf(px), fmaxf(fabsf(py), fabsf(pz)));
    if (nrm > 1.0f) {
        const float invn = 1.0f / nrm;
        const float sc = (1.2f - 0.2f * invn) * invn;
        px *= sc; py *= sc; pz *= sc;
    }
    float gx = (px - XYZ_MIN) * COORD_SCALE;
    float gy = (py - XYZ_MIN) * COORD_SCALE;
    float gz = (pz - XYZ_MIN) * COORD_SCALE;
    gx = fminf(fmaxf(gx, 0.0f), 159.0f);
    gy = fminf(fmaxf(gy, 0.0f), 159.0f);
    gz = fminf(fmaxf(gz, 0.0f), 159.0f);
    const int ix = min((int)floorf(gx), 158);
    const int iy = min((int)floorf(gy), 158);
    const int iz = min((int)floorf(gz), 158);
    const float fx = gx - (float)ix, fy = gy - (float)iy, fz = gz - (float)iz;
    const float ex = 1.0f - fx, ey = 1.0f - fy, ez = 1.0f - fz;
    const int base = ix * GRID_D2 + iy * GRID_D + iz;

    // ---- fp8 AoS gather: 4 corner-pairs, 32B contiguous each (z & z+1) ----
    float accd = 0.0f;
    __half2 acck[6];
#pragma unroll
    for (int j = 0; j < 6; j++) acck[j] = __float2half2_rn(0.0f);
    {
        const float wxy[4] = {ex * ey, ex * fy, fx * ey, fx * fy};
        const int vb[4] = {base, base + GRID_D, base + GRID_D2, base + GRID_D2 + GRID_D};
#pragma unroll
        for (int p = 0; p < 4; p++) {
            const uint4 q0 = PG[vb[p]];
            const uint4 q1 = PG[vb[p] + 1];
            const float wz0 = wxy[p] * ez, wz1 = wxy[p] * fz;
            accd += bflo(q0.x) * wz0 + bflo(q1.x) * wz1;
            const __half2 h0 = __float2half2_rn(wz0);
            const __half2 h1 = __float2half2_rn(wz1);
            acck[0] = __hfma2(e4m3x2_to_h2(q0.x >> 16), h0, acck[0]);
            acck[1] = __hfma2(e4m3x2_to_h2(q0.y), h0, acck[1]);
            acck[2] = __hfma2(e4m3x2_to_h2(q0.y >> 16), h0, acck[2]);
            acck[3] = __hfma2(e4m3x2_to_h2(q0.z), h0, acck[3]);
            acck[4] = __hfma2(e4m3x2_to_h2(q0.z >> 16), h0, acck[4]);
            acck[5] = __hfma2(e4m3x2_to_h2(q0.w), h0, acck[5]);
            acck[0] = __hfma2(e4m3x2_to_h2(q1.x >> 16), h1, acck[0]);
            acck[1] = __hfma2(e4m3x2_to_h2(q1.y), h1, acck[1]);
            acck[2] = __hfma2(e4m3x2_to_h2(q1.y >> 16), h1, acck[2]);
            acck[3] = __hfma2(e4m3x2_to_h2(q1.z), h1, acck[3]);
            acck[4] = __hfma2(e4m3x2_to_h2(q1.z >> 16), h1, acck[4]);
            acck[5] = __hfma2(e4m3x2_to_h2(q1.w), h1, acck[5]);
        }
    }

    // ---- density -> alpha ----
    {
        const float x = accd + ACT_SHIFT;
        const float sigma = fmaxf(x, 0.0f) + log1pf(__expf(-fabsf(x)));
        g_alpha[idx] = 1.0f - __expf(-sigma * STEPDIST);
    }

    // ---- features -> smem bf16x2, row = tid, stride 28 words ----
    {
        float feat[40];
#pragma unroll
        for (int j = 0; j < 6; j++) {
            const float2 kc = __half22float2(acck[j]);
            feat[2 * j] = kc.x;
            feat[2 * j + 1] = kc.y;
        }
        feat[12] = vx; feat[13] = vy; feat[14] = vz;
        {
            const float v3[3] = {vx, vy, vz};
#pragma unroll
            for (int i = 0; i < 3; i++) {
#pragma unroll
                for (int p = 0; p < 4; p++) {
                    float sv, cv;
                    __sincosf(v3[i] * (float)(1 << p), &sv, &cv);
                    feat[15 + i * 4 + p] = sv;
                    feat[27 + i * 4 + p] = cv;
                }
            }
        }
        feat[39] = 0.0f;
        uint32_t* F = smw + SM_F;
#pragma unroll
        for (int j = 0; j < 20; j++)
            F[tid * 28 + j] = pack_bf16x2(feat[2 * j], feat[2 * j + 1]);
#pragma unroll
        for (int j = 20; j < 24; j++) F[tid * 28 + j] = 0u;
    }

    __syncthreads();   // weights + features staged

    const int lane = tid & 31;
    const int warp = tid >> 5;
    const int g8 = lane >> 2;      // groupID 0..7
    const int q = lane & 3;        // threadID_in_group
    const int m0 = warp * 32;
    const int arow = lane & 7;     // ldmatrix row provider
    const int amt = lane >> 3;     // ldmatrix matrix selector

    const uint32_t sm_base = smem_u32(sm);
    const uint32_t Fb  = sm_base + SM_F * 4;
    const uint32_t W0b = sm_base + SM_W0T * 4;
    const uint32_t W1b = sm_base + SM_W1T * 4;

    // ---- A fragments for layer 0 via ldmatrix.x4 (6 instrs) ----
    uint32_t af[2][3][4];
#pragma unroll
    for (int t = 0; t < 2; t++) {
#pragma unroll
        for (int kk = 0; kk < 3; kk++) {
            const uint32_t addr = Fb +
                (((m0 + 16 * t + ((amt & 1) << 3) + arow) * 28 + 8 * kk + ((amt >> 1) << 2)) << 2);
            ldsm_x4(af[t][kk][0], af[t][kk][1], af[t][kk][2], af[t][kk][3], addr);
        }
    }

    // ---- layer 0: C fragments become layer-1 A fragments directly in registers ----
    uint32_t a1f[2][8][4];
#pragma unroll
    for (int nt = 0; nt < 16; nt++) {
        const int n0 = nt * 8;
        const float cb0 = sm[SM_B0 + n0 + 2 * q];
        const float cb1 = sm[SM_B0 + n0 + 2 * q + 1];
        float C0[4] = {cb0, cb1, cb0, cb1};
        float C1[4] = {cb0, cb1, cb0, cb1};
        uint32_t bb[6];
        ldsm_x4(bb[0], bb[1], bb[2], bb[3],
                W0b + (((n0 + arow) * 28 + (amt << 2)) << 2));
        ldsm_x2(bb[4], bb[5],
                W0b + (((n0 + arow) * 28 + 16 + ((amt & 1) << 2)) << 2));
#pragma unroll
        for (int kk = 0; kk < 3; kk++) {
            mma_bf16(C0, af[0][kk][0], af[0][kk][1], af[0][kk][2], af[0][kk][3],
                     bb[2 * kk], bb[2 * kk + 1]);
            mma_bf16(C1, af[1][kk][0], af[1][kk][1], af[1][kk][2], af[1][kk][3],
                     bb[2 * kk], bb[2 * kk + 1]);
        }
        const int kk1 = nt >> 1;
        const int hi = (nt & 1) << 1;
        a1f[0][kk1][hi]     = pack_bf16x2(fmaxf(C0[0], 0.0f), fmaxf(C0[1], 0.0f));
        a1f[0][kk1][hi + 1] = pack_bf16x2(fmaxf(C0[2], 0.0f), fmaxf(C0[3], 0.0f));
        a1f[1][kk1][hi]     = pack_bf16x2(fmaxf(C1[0], 0.0f), fmaxf(C1[1], 0.0f));
        a1f[1][kk1][hi + 1] = pack_bf16x2(fmaxf(C1[2], 0.0f), fmaxf(C1[3], 0.0f));
    }

    // ---- layer 1 + fused layer 2 ----
    float acc[4][3];
#pragma unroll
    for (int i = 0; i < 4; i++)
#pragma unroll
        for (int c = 0; c < 3; c++) acc[i][c] = 0.0f;

    const float* W2s = sm + SM_W2;
#pragma unroll
    for (int nt = 0; nt < 16; nt++) {
        const int n0 = nt * 8;
        const float cb0 = sm[SM_B1 + n0 + 2 * q];
        const float cb1 = sm[SM_B1 + n0 + 2 * q + 1];
        float C0[4] = {cb0, cb1, cb0, cb1};
        float C1[4] = {cb0, cb1, cb0, cb1};
#pragma unroll
        for (int kp = 0; kp < 4; kp++) {
            uint32_t w0r, w1r, w2r, w3r;
            ldsm_x4(w0r, w1r, w2r, w3r,
                    W1b + (((n0 + arow) * 68 + 16 * kp + (amt << 2)) << 2));
            const int kk = 2 * kp;
            mma_bf16(C0, a1f[0][kk][0], a1f[0][kk][1], a1f[0][kk][2], a1f[0][kk][3], w0r, w1r);
            mma_bf16(C1, a1f[1][kk][0], a1f[1][kk][1], a1f[1][kk][2], a1f[1][kk][3], w0r, w1r);
            mma_bf16(C0, a1f[0][kk + 1][0], a1f[0][kk + 1][1], a1f[0][kk + 1][2], a1f[0][kk + 1][3], w2r, w3r);
            mma_bf16(C1, a1f[1][kk + 1][0], a1f[1][kk + 1][1], a1f[1][kk + 1][2], a1f[1][kk + 1][3], w2r, w3r);
        }
        const int col0 = n0 + 2 * q, col1 = col0 + 1;
        const float w20x = W2s[col0 * 3 + 0], w20y = W2s[col0 * 3 + 1], w20z = W2s[col0 * 3 + 2];
        const float w21x = W2s[col1 * 3 + 0], w21y = W2s[col1 * 3 + 1], w21z = W2s[col1 * 3 + 2];
        {
            const float h0 = fmaxf(C0[0], 0.0f), h1 = fmaxf(C0[1], 0.0f);
            const float h2 = fmaxf(C0[2], 0.0f), h3 = fmaxf(C0[3], 0.0f);
            acc[0][0] += h0 * w20x + h1 * w21x;
            acc[0][1] += h0 * w20y + h1 * w21y;
            acc[0][2] += h0 * w20z + h1 * w21z;
            acc[1][0] += h2 * w20x + h3 * w21x;
            acc[1][1] += h2 * w20y + h3 * w21y;
            acc[1][2] += h2 * w20z + h3 * w21z;
        }
        {
            const float h0 = fmaxf(C1[0], 0.0f), h1 = fmaxf(C1[1], 0.0f);
            const float h2 = fmaxf(C1[2], 0.0f), h3 = fmaxf(C1[3], 0.0f);
            acc[2][0] += h0 * w20x + h1 * w21x;
            acc[2][1] += h0 * w20y + h1 * w21y;
            acc[2][2] += h0 * w20z + h1 * w21z;
            acc[3][0] += h2 * w20x + h3 * w21x;
            acc[3][1] += h2 * w20y + h3 * w21y;
            acc[3][2] += h2 * w20z + h3 * w21z;
        }
    }

    // quad reduction
#pragma unroll
    for (int i = 0; i < 4; i++)
#pragma unroll
        for (int c = 0; c < 3; c++) {
            acc[i][c] += __shfl_xor_sync(0xFFFFFFFFu, acc[i][c], 1);
            acc[i][c] += __shfl_xor_sync(0xFFFFFFFFu, acc[i][c], 2);
        }

    if (q == 0) {
        const float bb0 = sm[SM_B2 + 0], bb1 = sm[SM_B2 + 1], bb2 = sm[SM_B2 + 2];
        const int rows[4] = {m0 + g8, m0 + 8 + g8, m0 + 16 + g8, m0 + 24 + g8};
#pragma unroll
        for (int i = 0; i < 4; i++) {
            const int oidx = blockIdx.x * BLOCK + rows[i];
            g_rgb0[oidx] = 1.0f / (1.0f + __expf(-(acc[i][0] + bb0)));
            g_rgb1[oidx] = 1.0f / (1.0f + __expf(-(acc[i][1] + bb1)));
            g_rgb2[oidx] = 1.0f / (1.0f + __expf(-(acc[i][2] + bb2)));
        }
    }
}

// ---------------- compositing: one warp per ray ----------------
__global__ void __launch_bounds__(256)
composite_kernel(float* __restrict__ out)
{
    const int gwarp = (blockIdx.x * blockDim.x + threadIdx.x) >> 5;
    const int lane = threadIdx.x & 31;
    if (gwarp >= N_RAYS) return;
    const int r = gwarp;

    float T = 1.0f, wsum = 0.0f, a0 = 0.0f, a1 = 0.0f, a2 = 0.0f;
#pragma unroll
    for (int chunk = 0; chunk < N_SAMPLES / 32; chunk++) {
        const int off = r * N_SAMPLES + chunk * 32 + lane;
        const float alpha = g_alpha[off];
        const float c0 = g_rgb0[off];
        const float c1 = g_rgb1[off];
        const float c2 = g_rgb2[off];
        float p = 1.0f - alpha + 1e-10f;
#pragma unroll
        for (int d = 1; d < 32; d <<= 1) {
            const float up = __shfl_up_sync(0xFFFFFFFFu, p, d);
            if (lane >= d) p *= up;
        }
        float excl = __shfl_up_sync(0xFFFFFFFFu, p, 1);
        if (lane == 0) excl = 1.0f;
        const float w = alpha * T * excl;
        wsum += w;
        a0 += w * c0; a1 += w * c1; a2 += w * c2;
        T *= __shfl_sync(0xFFFFFFFFu, p, 31);
    }
#pragma unroll
    for (int d = 16; d > 0; d >>= 1) {
        wsum += __shfl_down_sync(0xFFFFFFFFu, wsum, d);
        a0 += __shfl_down_sync(0xFFFFFFFFu, a0, d);
        a1 += __shfl_down_sync(0xFFFFFFFFu, a1, d);
        a2 += __shfl_down_sync(0xFFFFFFFFu, a2, d);
    }
    if (lane == 0) {
        const float bg = 1.0f - wsum;
        out[r * 3 + 0] = a0 + bg;
        out[r * 3 + 1] = a1 + bg;
        out[r * 3 + 2] = a2 + bg;
    }
}

extern "C" void kernel_launch(void* const* d_in, const int* in_sizes, int n_in,
                              void* d_out, int out_size)
{
    const float* rays_o = (const float*)d_in[0];
    const float* rays_d = (const float*)d_in[1];
    const float* dgrid  = (const float*)d_in[2];
    const float* k0grid = (const float*)d_in[3];
    const float* w0 = (const float*)d_in[4];
    const float* b0 = (const float*)d_in[5];
    const float* w1 = (const float*)d_in[6];
    const float* b1 = (const float*)d_in[7];
    const float* w2 = (const float*)d_in[8];
    const float* b2 = (const float*)d_in[9];
    float* out = (float*)d_out;

    cudaFuncSetAttribute(point_kernel,
                         cudaFuncAttributeMaxDynamicSharedMemorySize, SMEM_BYTES);

    prep_kernel<<<48, 256>>>(w0, w1);
    pack_grid_kernel<<<(GRID_D3 + 255) / 256, 256>>>(dgrid, k0grid);
    point_kernel<<<NPTS / BLOCK, BLOCK, SMEM_BYTES>>>(rays_o, rays_d, w2, b0, b1, b2);
    composite_kernel<<<(N_RAYS * 32 + 255) / 256, 256>>>(out);
}

// round 13
// speedup vs baseline: 9.8136x; 1.0015x over previous
#include <cuda_runtime.h>
#include <cuda_fp16.h>
#include <cstdint>
#include <math.h>

#define N_RAYS 4096
#define N_SAMPLES 192
#define GRID_D 160
#define GRID_D2 (160*160)
#define GRID_D3 (160*160*160)
#define K0_DIM 12
#define XYZ_MIN (-1.2f)
#define COORD_SCALE (159.0f / 2.4f)
#define ACT_SHIFT (-4.595119850134589f)
#define STEPDIST (2.8f / 192.0f)
#define NEARV 0.2f
#define FARV 3.0f

#define NPTS (N_RAYS * N_SAMPLES)
#define BLOCK 256
#define NTILES (NPTS / BLOCK)      /* 3072 */
#define GRID_P 296                 /* 2 CTAs x 148 SMs persistent */

// ---------------- scratch ----------------
__device__ float g_alpha[NPTS];
__device__ float g_rgb0[NPTS];
__device__ float g_rgb1[NPTS];
__device__ float g_rgb2[NPTS];
__device__ uint32_t PW0T[128 * 28];   // [n][kpair] bf16x2, k<39 real (pad to 48)
__device__ uint32_t PW1T[128 * 68];   // [n][kpair] bf16x2, k<128 real
// packed voxel: 16B = [density bf16 | k0[0..11] e4m3 | pad16]
__device__ uint4 PG[GRID_D3];         // 65.5 MB (L2-resident)

// ---------------- smem layout (4-byte word units) ----------------
#define SM_W0T 0                       /* 3584 */
#define SM_W1T 3584                    /* 8704 */
#define SM_F   12288                   /* 256*28 = 7168 */
#define SM_W2  19456                   /* 384 */
#define SM_B0  19840
#define SM_B1  19968
#define SM_B2  20096
#define SM_G   20100                   /* gather buf: 8 x 256 x uint4 = 8192 words */
#define SM_WORDS (SM_G + 8192)
#define SMEM_BYTES (SM_WORDS * 4)      /* ~110.5 KB -> 2 CTAs/SM */

__device__ __forceinline__ uint32_t pack_bf16x2(float lo, float hi) {
    uint32_t u;
    asm("cvt.rn.bf16x2.f32 %0, %1, %2;" : "=r"(u) : "f"(hi), "f"(lo));
    return u;
}
__device__ __forceinline__ float bflo(uint32_t u) { return __uint_as_float(u << 16); }

__device__ __forceinline__ uint16_t pack_e4m3x2(float lo, float hi) {
    uint16_t r;
    asm("cvt.rn.satfinite.e4m3x2.f32 %0, %1, %2;" : "=h"(r) : "f"(hi), "f"(lo));
    return r;
}
__device__ __forceinline__ __half2 e4m3x2_to_h2(uint32_t u) {
    uint32_t h2;
    asm("cvt.rn.f16x2.e4m3x2 %0, %1;" : "=r"(h2) : "h"((uint16_t)(u)));
    return *reinterpret_cast<__half2*>(&h2);
}

__device__ __forceinline__ uint32_t smem_u32(const void* p) {
    uint32_t a;
    asm("{ .reg .u64 t; cvta.to.shared.u64 t, %1; cvt.u32.u64 %0, t; }" : "=r"(a) : "l"(p));
    return a;
}
__device__ __forceinline__ void ldsm_x4(uint32_t& r0, uint32_t& r1, uint32_t& r2, uint32_t& r3,
                                        uint32_t addr) {
    asm volatile("ldmatrix.sync.aligned.m8n8.x4.shared.b16 {%0,%1,%2,%3}, [%4];"
                 : "=r"(r0), "=r"(r1), "=r"(r2), "=r"(r3) : "r"(addr));
}
__device__ __forceinline__ void ldsm_x2(uint32_t& r0, uint32_t& r1, uint32_t addr) {
    asm volatile("ldmatrix.sync.aligned.m8n8.x2.shared.b16 {%0,%1}, [%2];"
                 : "=r"(r0), "=r"(r1) : "r"(addr));
}
__device__ __forceinline__ void mma_bf16(float c[4],
                                         uint32_t a0, uint32_t a1, uint32_t a2, uint32_t a3,
                                         uint32_t b0, uint32_t b1) {
    asm volatile("mma.sync.aligned.m16n8k16.row.col.f32.bf16.bf16.f32 "
                 "{%0,%1,%2,%3}, {%4,%5,%6,%7}, {%8,%9}, {%0,%1,%2,%3};"
                 : "+f"(c[0]), "+f"(c[1]), "+f"(c[2]), "+f"(c[3])
                 : "r"(a0), "r"(a1), "r"(a2), "r"(a3), "r"(b0), "r"(b1));
}
#define CP_ASYNC16(dst, src) \
    asm volatile("cp.async.cg.shared.global [%0], [%1], 16;" :: "r"(dst), "l"(src))
#define CP_COMMIT() asm volatile("cp.async.commit_group;" ::: "memory")
#define CP_WAIT0()  asm volatile("cp.async.wait_group 0;" ::: "memory")

// ---------------- pack grids (+ weight prep folded in) ----------------
__global__ void __launch_bounds__(256)
pack_grid_kernel(const float* __restrict__ dgrid, const float* __restrict__ k0grid,
                 const float* __restrict__ w0, const float* __restrict__ w1)
{
    const int gid = blockIdx.x * blockDim.x + threadIdx.x;
    if (gid < 128 * 28) {
        const int n = gid / 28, wd = gid - n * 28;
        const int k = 2 * wd;
        const float lo = (k < 39) ? w0[k * 128 + n] : 0.0f;
        const float hi = (k + 1 < 39) ? w0[(k + 1) * 128 + n] : 0.0f;
        PW0T[gid] = pack_bf16x2(lo, hi);
    } else if (gid < 128 * 28 + 128 * 68) {
        const int i = gid - 128 * 28;
        const int n = i / 68, wd = i - n * 68;
        const int k = 2 * wd;
        const float lo = (k < 128) ? w1[k * 128 + n] : 0.0f;
        const float hi = (k + 1 < 128) ? w1[(k + 1) * 128 + n] : 0.0f;
        PW1T[i] = pack_bf16x2(lo, hi);
    }
    const int v = gid;
    if (v >= GRID_D3) return;
    const float d = dgrid[v];
    float k[12];
#pragma unroll
    for (int c = 0; c < K0_DIM; c++) k[c] = k0grid[c * GRID_D3 + v];
    const uint32_t dbf = pack_bf16x2(d, 0.0f) & 0xffffu;
    const uint32_t a = dbf | ((uint32_t)pack_e4m3x2(k[0], k[1]) << 16);
    const uint32_t b = (uint32_t)pack_e4m3x2(k[2], k[3]) | ((uint32_t)pack_e4m3x2(k[4], k[5]) << 16);
    const uint32_t c = (uint32_t)pack_e4m3x2(k[6], k[7]) | ((uint32_t)pack_e4m3x2(k[8], k[9]) << 16);
    const uint32_t e = (uint32_t)pack_e4m3x2(k[10], k[11]);
    PG[v] = make_uint4(a, b, c, e);
}

// ---------------- persistent point kernel ----------------
__global__ void __launch_bounds__(BLOCK, 2)
point_kernel(const float* __restrict__ rays_o,
             const float* __restrict__ rays_d,
             const float* __restrict__ w2,
             const float* __restrict__ b0,
             const float* __restrict__ b1,
             const float* __restrict__ b2)
{
    extern __shared__ float sm[];
    uint32_t* smw = (uint32_t*)sm;
    const int tid = threadIdx.x;
    const uint32_t sm_base = smem_u32(sm);
    const uint32_t gdst0 = sm_base + SM_G * 4 + (uint32_t)tid * 16;

    // ---- stage weights ONCE per CTA ----
    {
        float4* d0 = (float4*)(smw + SM_W0T);
        const float4* s0 = (const float4*)PW0T;
        for (int i = tid; i < 896; i += BLOCK) d0[i] = s0[i];
        float4* d1 = (float4*)(smw + SM_W1T);
        const float4* s1 = (const float4*)PW1T;
        for (int i = tid; i < 2176; i += BLOCK) d1[i] = s1[i];
    }
    for (int i = tid; i < 384; i += BLOCK) sm[SM_W2 + i] = w2[i];
    if (tid < 128) {
        sm[SM_B0 + tid] = b0[tid];
        sm[SM_B1 + tid] = b1[tid];
    }
    if (tid < 3) sm[SM_B2 + tid] = b2[tid];

    const int lane = tid & 31;
    const int warp = tid >> 5;
    const int g8 = lane >> 2;
    const int q = lane & 3;
    const int m0 = warp * 32;
    const int arow = lane & 7;
    const int amt = lane >> 3;
    const uint32_t Fb  = sm_base + SM_F * 4;
    const uint32_t W0b = sm_base + SM_W0T * 4;
    const uint32_t W1b = sm_base + SM_W1T * 4;
    const uint4* gbuf = (const uint4*)(smw + SM_G);

    // pipelined geometry state for the in-flight tile
    float wxy0, wxy1, wxy2, wxy3, ezr, fzr, pvx, pvy, pvz;
    int sidx;

    int t = blockIdx.x;

    // ---- issue geometry + gather for a tile ----
    auto issue = [&](int tt) {
        const int idx = tt * BLOCK + tid;
        const int r = idx / N_SAMPLES;
        const int s = idx - r * N_SAMPLES;
        float dx = rays_d[r * 3 + 0], dy = rays_d[r * 3 + 1], dz = rays_d[r * 3 + 2];
        const float inv = rsqrtf(dx * dx + dy * dy + dz * dz);
        const float vx = dx * inv, vy = dy * inv, vz = dz * inv;
        const float tval = NEARV + (FARV - NEARV) * ((float)s + 0.5f) / (float)N_SAMPLES;
        float px = rays_o[r * 3 + 0] + vx * tval;
        float py = rays_o[r * 3 + 1] + vy * tval;
        float pz = rays_o[r * 3 + 2] + vz * tval;
        const float nrm = fmaxf(fabsf(px), fmaxf(fabsf(py), fabsf(pz)));
        if (nrm > 1.0f) {
            const float invn = 1.0f / nrm;
            const float sc = (1.2f - 0.2f * invn) * invn;
            px *= sc; py *= sc; pz *= sc;
        }
        float gx = (px - XYZ_MIN) * COORD_SCALE;
        float gy = (py - XYZ_MIN) * COORD_SCALE;
        float gz = (pz - XYZ_MIN) * COORD_SCALE;
        gx = fminf(fmaxf(gx, 0.0f), 159.0f);
        gy = fminf(fmaxf(gy, 0.0f), 159.0f);
        gz = fminf(fmaxf(gz, 0.0f), 159.0f);
        const int ix = min((int)floorf(gx), 158);
        const int iy = min((int)floorf(gy), 158);
        const int iz = min((int)floorf(gz), 158);
        const float fx = gx - (float)ix, fy = gy - (float)iy, fz = gz - (float)iz;
        const float ex = 1.0f - fx, ey = 1.0f - fy;
        const int base = ix * GRID_D2 + iy * GRID_D + iz;
        wxy0 = ex * ey; wxy1 = ex * fy; wxy2 = fx * ey; wxy3 = fx * fy;
        ezr = 1.0f - fz; fzr = fz;
        pvx = vx; pvy = vy; pvz = vz;
        sidx = idx;
        const int vb[4] = {base, base + GRID_D, base + GRID_D2, base + GRID_D2 + GRID_D};
#pragma unroll
        for (int p = 0; p < 4; p++) {
            const char* src = (const char*)(PG + vb[p]);
            CP_ASYNC16(gdst0 + (uint32_t)(2 * p) * 4096u, src);
            CP_ASYNC16(gdst0 + (uint32_t)(2 * p + 1) * 4096u, src + 16);
        }
    };

    issue(t);
    CP_COMMIT();
    __syncthreads();   // weights staged (gather for tile 0 still in flight)

    while (true) {
        CP_WAIT0();

        // ---- decode gather buffer -> density + k0 features ----
        float accd = 0.0f;
        __half2 acck[6];
#pragma unroll
        for (int j = 0; j < 6; j++) acck[j] = __float2half2_rn(0.0f);
        {
            const float wxy[4] = {wxy0, wxy1, wxy2, wxy3};
#pragma unroll
            for (int p = 0; p < 4; p++) {
                const uint4 q0 = gbuf[(2 * p) * 256 + tid];
                const uint4 q1 = gbuf[(2 * p + 1) * 256 + tid];
                const float wz0 = wxy[p] * ezr, wz1 = wxy[p] * fzr;
                accd += bflo(q0.x) * wz0 + bflo(q1.x) * wz1;
                const __half2 h0 = __float2half2_rn(wz0);
                const __half2 h1 = __float2half2_rn(wz1);
                acck[0] = __hfma2(e4m3x2_to_h2(q0.x >> 16), h0, acck[0]);
                acck[1] = __hfma2(e4m3x2_to_h2(q0.y), h0, acck[1]);
                acck[2] = __hfma2(e4m3x2_to_h2(q0.y >> 16), h0, acck[2]);
                acck[3] = __hfma2(e4m3x2_to_h2(q0.z), h0, acck[3]);
                acck[4] = __hfma2(e4m3x2_to_h2(q0.z >> 16), h0, acck[4]);
                acck[5] = __hfma2(e4m3x2_to_h2(q0.w), h0, acck[5]);
                acck[0] = __hfma2(e4m3x2_to_h2(q1.x >> 16), h1, acck[0]);
                acck[1] = __hfma2(e4m3x2_to_h2(q1.y), h1, acck[1]);
                acck[2] = __hfma2(e4m3x2_to_h2(q1.y >> 16), h1, acck[2]);
                acck[3] = __hfma2(e4m3x2_to_h2(q1.z), h1, acck[3]);
                acck[4] = __hfma2(e4m3x2_to_h2(q1.z >> 16), h1, acck[4]);
                acck[5] = __hfma2(e4m3x2_to_h2(q1.w), h1, acck[5]);
            }
        }
        {
            const float x = accd + ACT_SHIFT;
            const float sigma = fmaxf(x, 0.0f) + log1pf(__expf(-fabsf(x)));
            g_alpha[sidx] = 1.0f - __expf(-sigma * STEPDIST);
        }

        // ---- features -> F smem (rows warp-private) ----
        {
            float feat[40];
#pragma unroll
            for (int j = 0; j < 6; j++) {
                const float2 kc = __half22float2(acck[j]);
                feat[2 * j] = kc.x;
                feat[2 * j + 1] = kc.y;
            }
            feat[12] = pvx; feat[13] = pvy; feat[14] = pvz;
            {
                const float v3[3] = {pvx, pvy, pvz};
#pragma unroll
                for (int i = 0; i < 3; i++) {
#pragma unroll
                    for (int p = 0; p < 4; p++) {
                        float sv, cv;
                        __sincosf(v3[i] * (float)(1 << p), &sv, &cv);
                        feat[15 + i * 4 + p] = sv;
                        feat[27 + i * 4 + p] = cv;
                    }
                }
            }
            feat[39] = 0.0f;
            uint32_t* F = smw + SM_F;
#pragma unroll
            for (int j = 0; j < 20; j++)
                F[tid * 28 + j] = pack_bf16x2(feat[2 * j], feat[2 * j + 1]);
#pragma unroll
            for (int j = 20; j < 24; j++) F[tid * 28 + j] = 0u;
        }
        __syncwarp();

        // ---- issue next tile's gather (flies under the MLP below) ----
        const int tcur = t;
        const int tn = t + GRID_P;
        const bool have_next = (tn < NTILES);
        if (have_next) {
            t = tn;
            issue(tn);
            CP_COMMIT();
        }

        // ---- layer 0 (A via ldmatrix; C -> layer-1 A fragments in registers) ----
        uint32_t af[2][3][4];
#pragma unroll
        for (int tt = 0; tt < 2; tt++) {
#pragma unroll
            for (int kk = 0; kk < 3; kk++) {
                const uint32_t addr = Fb +
                    (((m0 + 16 * tt + ((amt & 1) << 3) + arow) * 28 + 8 * kk + ((amt >> 1) << 2)) << 2);
                ldsm_x4(af[tt][kk][0], af[tt][kk][1], af[tt][kk][2], af[tt][kk][3], addr);
            }
        }
        uint32_t a1f[2][8][4];
#pragma unroll
        for (int nt = 0; nt < 16; nt++) {
            const int n0 = nt * 8;
            const float cb0 = sm[SM_B0 + n0 + 2 * q];
            const float cb1 = sm[SM_B0 + n0 + 2 * q + 1];
            float C0[4] = {cb0, cb1, cb0, cb1};
            float C1[4] = {cb0, cb1, cb0, cb1};
            uint32_t bb[6];
            ldsm_x4(bb[0], bb[1], bb[2], bb[3],
                    W0b + (((n0 + arow) * 28 + (amt << 2)) << 2));
            ldsm_x2(bb[4], bb[5],
                    W0b + (((n0 + arow) * 28 + 16 + ((amt & 1) << 2)) << 2));
#pragma unroll
            for (int kk = 0; kk < 3; kk++) {
                mma_bf16(C0, af[0][kk][0], af[0][kk][1], af[0][kk][2], af[0][kk][3],
                         bb[2 * kk], bb[2 * kk + 1]);
                mma_bf16(C1, af[1][kk][0], af[1][kk][1], af[1][kk][2], af[1][kk][3],
                         bb[2 * kk], bb[2 * kk + 1]);
            }
            const int kk1 = nt >> 1;
            const int hi = (nt & 1) << 1;
            a1f[0][kk1][hi]     = pack_bf16x2(fmaxf(C0[0], 0.0f), fmaxf(C0[1], 0.0f));
            a1f[0][kk1][hi + 1] = pack_bf16x2(fmaxf(C0[2], 0.0f), fmaxf(C0[3], 0.0f));
            a1f[1][kk1][hi]     = pack_bf16x2(fmaxf(C1[0], 0.0f), fmaxf(C1[1], 0.0f));
            a1f[1][kk1][hi + 1] = pack_bf16x2(fmaxf(C1[2], 0.0f), fmaxf(C1[3], 0.0f));
        }

        // ---- layer 1 + fused layer 2 ----
        float acc[4][3];
#pragma unroll
        for (int i = 0; i < 4; i++)
#pragma unroll
            for (int c = 0; c < 3; c++) acc[i][c] = 0.0f;

        const float* W2s = sm + SM_W2;
#pragma unroll
        for (int nt = 0; nt < 16; nt++) {
            const int n0 = nt * 8;
            const float cb0 = sm[SM_B1 + n0 + 2 * q];
            const float cb1 = sm[SM_B1 + n0 + 2 * q + 1];
            float C0[4] = {cb0, cb1, cb0, cb1};
            float C1[4] = {cb0, cb1, cb0, cb1};
#pragma unroll
            for (int kp = 0; kp < 4; kp++) {
                uint32_t w0r, w1r, w2r, w3r;
                ldsm_x4(w0r, w1r, w2r, w3r,
                        W1b + (((n0 + arow) * 68 + 16 * kp + (amt << 2)) << 2));
                const int kk = 2 * kp;
                mma_bf16(C0, a1f[0][kk][0], a1f[0][kk][1], a1f[0][kk][2], a1f[0][kk][3], w0r, w1r);
                mma_bf16(C1, a1f[1][kk][0], a1f[1][kk][1], a1f[1][kk][2], a1f[1][kk][3], w0r, w1r);
                mma_bf16(C0, a1f[0][kk + 1][0], a1f[0][kk + 1][1], a1f[0][kk + 1][2], a1f[0][kk + 1][3], w2r, w3r);
                mma_bf16(C1, a1f[1][kk + 1][0], a1f[1][kk + 1][1], a1f[1][kk + 1][2], a1f[1][kk + 1][3], w2r, w3r);
            }
            const int col0 = n0 + 2 * q, col1 = col0 + 1;
            const float w20x = W2s[col0 * 3 + 0], w20y = W2s[col0 * 3 + 1], w20z = W2s[col0 * 3 + 2];
            const float w21x = W2s[col1 * 3 + 0], w21y = W2s[col1 * 3 + 1], w21z = W2s[col1 * 3 + 2];
            {
                const float h0 = fmaxf(C0[0], 0.0f), h1 = fmaxf(C0[1], 0.0f);
                const float h2 = fmaxf(C0[2], 0.0f), h3 = fmaxf(C0[3], 0.0f);
                acc[0][0] += h0 * w20x + h1 * w21x;
                acc[0][1] += h0 * w20y + h1 * w21y;
                acc[0][2] += h0 * w20z + h1 * w21z;
                acc[1][0] += h2 * w20x + h3 * w21x;
                acc[1][1] += h2 * w20y + h3 * w21y;
                acc[1][2] += h2 * w20z + h3 * w21z;
            }
            {
                const float h0 = fmaxf(C1[0], 0.0f), h1 = fmaxf(C1[1], 0.0f);
                const float h2 = fmaxf(C1[2], 0.0f), h3 = fmaxf(C1[3], 0.0f);
                acc[2][0] += h0 * w20x + h1 * w21x;
                acc[2][1] += h0 * w20y + h1 * w21y;
                acc[2][2] += h0 * w20z + h1 * w21z;
                acc[3][0] += h2 * w20x + h3 * w21x;
                acc[3][1] += h2 * w20y + h3 * w21y;
                acc[3][2] += h2 * w20z + h3 * w21z;
            }
        }

#pragma unroll
        for (int i = 0; i < 4; i++)
#pragma unroll
            for (int c = 0; c < 3; c++) {
                acc[i][c] += __shfl_xor_sync(0xFFFFFFFFu, acc[i][c], 1);
                acc[i][c] += __shfl_xor_sync(0xFFFFFFFFu, acc[i][c], 2);
            }

        if (q == 0) {
            const float bb0 = sm[SM_B2 + 0], bb1 = sm[SM_B2 + 1], bb2 = sm[SM_B2 + 2];
            const int rows[4] = {m0 + g8, m0 + 8 + g8, m0 + 16 + g8, m0 + 24 + g8};
#pragma unroll
            for (int i = 0; i < 4; i++) {
                const int oidx = tcur * BLOCK + rows[i];
                g_rgb0[oidx] = 1.0f / (1.0f + __expf(-(acc[i][0] + bb0)));
                g_rgb1[oidx] = 1.0f / (1.0f + __expf(-(acc[i][1] + bb1)));
                g_rgb2[oidx] = 1.0f / (1.0f + __expf(-(acc[i][2] + bb2)));
            }
        }
        __syncwarp();   // all lanes done reading F rows before next iter overwrites

        if (!have_next) break;
    }
}

// ---------------- compositing: one warp per ray ----------------
__global__ void __launch_bounds__(256)
composite_kernel(float* __restrict__ out)
{
    const int gwarp = (blockIdx.x * blockDim.x + threadIdx.x) >> 5;
    const int lane = threadIdx.x & 31;
    if (gwarp >= N_RAYS) return;
    const int r = gwarp;

    float T = 1.0f, wsum = 0.0f, a0 = 0.0f, a1 = 0.0f, a2 = 0.0f;
#pragma unroll
    for (int chunk = 0; chunk < N_SAMPLES / 32; chunk++) {
        const int off = r * N_SAMPLES + chunk * 32 + lane;
        const float alpha = g_alpha[off];
        const float c0 = g_rgb0[off];
        const float c1 = g_rgb1[off];
        const float c2 = g_rgb2[off];
        float p = 1.0f - alpha + 1e-10f;
#pragma unroll
        for (int d = 1; d < 32; d <<= 1) {
            const float up = __shfl_up_sync(0xFFFFFFFFu, p, d);
            if (lane >= d) p *= up;
        }
        float excl = __shfl_up_sync(0xFFFFFFFFu, p, 1);
        if (lane == 0) excl = 1.0f;
        const float w = alpha * T * excl;
        wsum += w;
        a0 += w * c0; a1 += w * c1; a2 += w * c2;
        T *= __shfl_sync(0xFFFFFFFFu, p, 31);
    }
#pragma unroll
    for (int d = 16; d > 0; d >>= 1) {
        wsum += __shfl_down_sync(0xFFFFFFFFu, wsum, d);
        a0 += __shfl_down_sync(0xFFFFFFFFu, a0, d);
        a1 += __shfl_down_sync(0xFFFFFFFFu, a1, d);
        a2 += __shfl_down_sync(0xFFFFFFFFu, a2, d);
    }
    if (lane == 0) {
        const float bg = 1.0f - wsum;
        out[r * 3 + 0] = a0 + bg;
        out[r * 3 + 1] = a1 + bg;
        out[r * 3 + 2] = a2 + bg;
    }
}

extern "C" void kernel_launch(void* const* d_in, const int* in_sizes, int n_in,
                              void* d_out, int out_size)
{
    const float* rays_o = (const float*)d_in[0];
    const float* rays_d = (const float*)d_in[1];
    const float* dgrid  = (const float*)d_in[2];
    const float* k0grid = (const float*)d_in[3];
    const float* w0 = (const float*)d_in[4];
    const float* b0 = (const float*)d_in[5];
    const float* w1 = (const float*)d_in[6];
    const float* b1 = (const float*)d_in[7];
    const float* w2 = (const float*)d_in[8];
    const float* b2 = (const float*)d_in[9];
    float* out = (float*)d_out;

    cudaFuncSetAttribute(point_kernel,
                         cudaFuncAttributeMaxDynamicSharedMemorySize, SMEM_BYTES);

    pack_grid_kernel<<<(GRID_D3 + 255) / 256, 256>>>(dgrid, k0grid, w0, w1);
    point_kernel<<<GRID_P, BLOCK, SMEM_BYTES>>>(rays_o, rays_d, w2, b0, b1, b2);
    composite_kernel<<<(N_RAYS * 32 + 255) / 256, 256>>>(out);
}